// round 5
// baseline (speedup 1.0000x reference)
#include <cuda_runtime.h>
#include <math.h>

#define NB 8
#define C 256
#define HW 1024
#define TN 1024
#define HIDDEN 1024

// ---------------- scratch ----------------
__device__ float g_qbranch[NB*C*HW];
__device__ float g_kvbranch[NB*C*HW];
__device__ float g_tmp[NB*C*HW];
__device__ float g_qb[NB*C*HW];
__device__ float g_kb[NB*C*HW];
__device__ float g_vb[NB*C*HW];
__device__ float g_attn[NB*C*HW];
__device__ float g_h1[NB*HIDDEN*HW];   // also: conv split-K partials / qkv-free scratch
__device__ float g_h2[NB*HIDDEN*HW];   // also: fused qkv output

// ---------------- f32x2 helpers ----------------
__device__ __forceinline__ void ffma2(unsigned long long& d, unsigned long long a, unsigned long long b) {
    asm("fma.rn.f32x2 %0, %1, %2, %0;" : "+l"(d) : "l"(a), "l"(b));
}
__device__ __forceinline__ void mul2(unsigned long long& d, unsigned long long a) {
    asm("mul.rn.f32x2 %0, %0, %1;" : "+l"(d) : "l"(a));
}
__device__ __forceinline__ unsigned long long pk2(float x) {
    unsigned u = __float_as_uint(x);
    unsigned long long r;
    asm("mov.b64 %0, {%1, %1};" : "=l"(r) : "r"(u));
    return r;
}
__device__ __forceinline__ float lo2(unsigned long long v){ return __uint_as_float((unsigned)v); }
__device__ __forceinline__ float hi2(unsigned long long v){ return __uint_as_float((unsigned)(v >> 32)); }

// ---------------- cp.async helpers ----------------
__device__ __forceinline__ void cp16(void* dst, const void* src) {
    unsigned d = (unsigned)__cvta_generic_to_shared(dst);
    asm volatile("cp.async.ca.shared.global [%0], [%1], 16;" :: "r"(d), "l"(src));
}
__device__ __forceinline__ void cp4z(void* dst, const void* src, int sz) {
    unsigned d = (unsigned)__cvta_generic_to_shared(dst);
    asm volatile("cp.async.ca.shared.global [%0], [%1], 4, %2;" :: "r"(d), "l"(src), "r"(sz));
}
__device__ __forceinline__ void cp_commit() { asm volatile("cp.async.commit_group;" ::: "memory"); }
__device__ __forceinline__ void cp_wait0()  { asm volatile("cp.async.wait_group 0;" ::: "memory"); }

// ---------------- shared 64x128 f32x2 tile compute ----------------
__device__ __forceinline__ void mm_tile(
    const float (*As)[64], const float (*Bs)[128],
    unsigned long long accp[4][8], int tm0, int cw)
{
    #pragma unroll 4
    for (int k = 0; k < 16; k++) {
        ulonglong2 a01 = *(const ulonglong2*)&As[k][tm0];
        ulonglong2 a23 = *(const ulonglong2*)&As[k][tm0 + 4];
        float4 b0 = *(const float4*)&Bs[k][cw];
        float4 b1 = *(const float4*)&Bs[k][cw + 32];
        unsigned long long ap[4] = {a01.x, a01.y, a23.x, a23.y};
        unsigned long long bb[8] = {pk2(b0.x), pk2(b0.y), pk2(b0.z), pk2(b0.w),
                                    pk2(b1.x), pk2(b1.y), pk2(b1.z), pk2(b1.w)};
        #pragma unroll
        for (int i = 0; i < 4; i++)
            #pragma unroll
            for (int j = 0; j < 8; j++)
                ffma2(accp[i][j], ap[i], bb[j]);
    }
}

// ---------------- batched SGEMM: tile 64(M)x128(N), 128 thr, dbl-buffered ----------------
// grid: (TN/128, M/64, NB*S). If S>1: output to partials at (s*NB+b)*M*TN, add must be null.
__global__ __launch_bounds__(128) void sgemm_f2(
    const float* __restrict__ A, const float* __restrict__ B,
    float* Cd, const float* addp, int M, int K, int S)
{
    __shared__ float As[2][16][64];
    __shared__ float Bs[2][16][128];

    int bz = blockIdx.z;
    int s = bz >> 3, b = bz & 7;
    int bn = blockIdx.x * 128;
    int bm = blockIdx.y * 64;
    int Klen = K / S;
    int k0 = s * Klen;

    const float* Bb = B + (size_t)b * K * TN;
    float*       Cb = Cd + (size_t)(s * NB + b) * M * TN;
    const float* addb = addp ? addp + (size_t)b * M * TN : nullptr;

    int tid = threadIdx.x;
    int warp = tid >> 5, lane = tid & 31;
    int wm = warp >> 1, wn = warp & 1;
    int lm = lane >> 3, ln = lane & 7;
    int tm0 = wm * 32 + lm * 8;
    int cw  = wn * 64 + ln * 4;

    int am = tid & 63, akc = (tid >> 6) * 8;
    const float* aptr = A + (size_t)(bm + am) * K + k0 + akc;

    unsigned long long accp[4][8] = {};

    // prologue
    float4 a0 = *(const float4*)(aptr);
    float4 a1 = *(const float4*)(aptr + 4);
    {
        int kb = (tid >> 5) * 4, n4 = (tid & 31) * 4;
        #pragma unroll
        for (int e = 0; e < 4; e++)
            cp16(&Bs[0][kb + e][n4], Bb + (size_t)(k0 + kb + e) * TN + bn + n4);
    }
    cp_commit();
    #pragma unroll
    for (int j = 0; j < 4; j++) { As[0][akc + j][am] = ((const float*)&a0)[j]; As[0][akc + 4 + j][am] = ((const float*)&a1)[j]; }
    cp_wait0();
    __syncthreads();

    int nk = Klen / 16;
    int buf = 0;
    for (int kt = 0; kt < nk; kt++) {
        bool more = (kt + 1) < nk;
        if (more) {
            const float* ap2 = aptr + (kt + 1) * 16;
            a0 = *(const float4*)(ap2);
            a1 = *(const float4*)(ap2 + 4);
            int kb = (tid >> 5) * 4, n4 = (tid & 31) * 4;
            int kk = k0 + (kt + 1) * 16;
            #pragma unroll
            for (int e = 0; e < 4; e++)
                cp16(&Bs[buf ^ 1][kb + e][n4], Bb + (size_t)(kk + kb + e) * TN + bn + n4);
            cp_commit();
        }
        mm_tile(As[buf], Bs[buf], accp, tm0, cw);
        if (more) {
            #pragma unroll
            for (int j = 0; j < 4; j++) { As[buf ^ 1][akc + j][am] = ((const float*)&a0)[j]; As[buf ^ 1][akc + 4 + j][am] = ((const float*)&a1)[j]; }
            cp_wait0();
        }
        __syncthreads();
        buf ^= 1;
    }

    // epilogue
    #pragma unroll
    for (int mp = 0; mp < 4; mp++) {
        int r = bm + tm0 + 2 * mp;
        float4 vlo1 = make_float4(lo2(accp[mp][0]), lo2(accp[mp][1]), lo2(accp[mp][2]), lo2(accp[mp][3]));
        float4 vhi1 = make_float4(hi2(accp[mp][0]), hi2(accp[mp][1]), hi2(accp[mp][2]), hi2(accp[mp][3]));
        float4 vlo2 = make_float4(lo2(accp[mp][4]), lo2(accp[mp][5]), lo2(accp[mp][6]), lo2(accp[mp][7]));
        float4 vhi2 = make_float4(hi2(accp[mp][4]), hi2(accp[mp][5]), hi2(accp[mp][6]), hi2(accp[mp][7]));
        size_t o1 = (size_t)r * TN + bn + cw;
        size_t o2 = o1 + 32;
        size_t o1b = o1 + TN, o2b = o2 + TN;
        if (addb) {
            float4 t;
            t = *(const float4*)(addb + o1);  vlo1.x += t.x; vlo1.y += t.y; vlo1.z += t.z; vlo1.w += t.w;
            t = *(const float4*)(addb + o2);  vlo2.x += t.x; vlo2.y += t.y; vlo2.z += t.z; vlo2.w += t.w;
            t = *(const float4*)(addb + o1b); vhi1.x += t.x; vhi1.y += t.y; vhi1.z += t.z; vhi1.w += t.w;
            t = *(const float4*)(addb + o2b); vhi2.x += t.x; vhi2.y += t.y; vhi2.z += t.z; vhi2.w += t.w;
        }
        *(float4*)(Cb + o1)  = vlo1;
        *(float4*)(Cb + o2)  = vlo2;
        *(float4*)(Cb + o1b) = vhi1;
        *(float4*)(Cb + o2b) = vhi2;
    }
}

// ---------------- conv KxK implicit GEMM, same tiling, split-K ----------------
template<int KW, int PAD>
__global__ __launch_bounds__(128) void conv_f2(
    const float* __restrict__ Wt, const float* __restrict__ X, float* __restrict__ Cd, int S)
{
    constexpr int KK2 = KW * KW;
    constexpr int K = C * KK2;
    __shared__ float As[2][16][64];
    __shared__ float Bs[2][16][128];

    int bz = blockIdx.z;
    int s = bz >> 3, b = bz & 7;
    int bn = blockIdx.x * 128;
    int bm = blockIdx.y * 64;
    int Klen = K / S;
    int k0 = s * Klen;

    const float* Xb = X + (size_t)b * C * HW;
    float*       Cb = Cd + (size_t)(s * NB + b) * C * HW;

    int tid = threadIdx.x;
    int warp = tid >> 5, lane = tid & 31;
    int wm = warp >> 1, wn = warp & 1;
    int lm = lane >> 3, ln = lane & 7;
    int tm0 = wm * 32 + lm * 8;
    int cw  = wn * 64 + ln * 4;

    int am = tid & 63, akc = (tid >> 6) * 8;
    const float* aptr = Wt + (size_t)(bm + am) * K + k0 + akc;

    int n = bn + tid;            // this thread's pixel column for B gather (tid<128)
    int yy = n >> 5, xx = n & 31;

    unsigned long long accp[4][8] = {};

    // B gather for one 16-k stage
    auto gatherB = [&](int buf, int kk) {
        #pragma unroll
        for (int e = 0; e < 16; e++) {
            int kg = kk + e;
            int ic = kg / KK2;
            int tap = kg - ic * KK2;
            int dy = tap / KW, dx = tap - dy * KW;
            int iy = yy + dy - PAD, ix = xx + dx - PAD;
            bool ok = ((unsigned)iy < 32u) && ((unsigned)ix < 32u);
            const float* src = Xb + (size_t)ic * HW + (ok ? ((iy << 5) + ix) : 0);
            cp4z(&Bs[buf][e][tid], src, ok ? 4 : 0);
        }
    };

    // prologue
    float4 a0 = *(const float4*)(aptr);
    float4 a1 = *(const float4*)(aptr + 4);
    gatherB(0, k0);
    cp_commit();
    #pragma unroll
    for (int j = 0; j < 4; j++) { As[0][akc + j][am] = ((const float*)&a0)[j]; As[0][akc + 4 + j][am] = ((const float*)&a1)[j]; }
    cp_wait0();
    __syncthreads();

    int nk = Klen / 16;
    int buf = 0;
    for (int kt = 0; kt < nk; kt++) {
        bool more = (kt + 1) < nk;
        if (more) {
            const float* ap2 = aptr + (kt + 1) * 16;
            a0 = *(const float4*)(ap2);
            a1 = *(const float4*)(ap2 + 4);
            gatherB(buf ^ 1, k0 + (kt + 1) * 16);
            cp_commit();
        }
        mm_tile(As[buf], Bs[buf], accp, tm0, cw);
        if (more) {
            #pragma unroll
            for (int j = 0; j < 4; j++) { As[buf ^ 1][akc + j][am] = ((const float*)&a0)[j]; As[buf ^ 1][akc + 4 + j][am] = ((const float*)&a1)[j]; }
            cp_wait0();
        }
        __syncthreads();
        buf ^= 1;
    }

    #pragma unroll
    for (int mp = 0; mp < 4; mp++) {
        int r = bm + tm0 + 2 * mp;
        size_t o1 = (size_t)r * TN + bn + cw;
        *(float4*)(Cb + o1)      = make_float4(lo2(accp[mp][0]), lo2(accp[mp][1]), lo2(accp[mp][2]), lo2(accp[mp][3]));
        *(float4*)(Cb + o1 + 32) = make_float4(lo2(accp[mp][4]), lo2(accp[mp][5]), lo2(accp[mp][6]), lo2(accp[mp][7]));
        *(float4*)(Cb + o1 + TN)      = make_float4(hi2(accp[mp][0]), hi2(accp[mp][1]), hi2(accp[mp][2]), hi2(accp[mp][3]));
        *(float4*)(Cb + o1 + TN + 32) = make_float4(hi2(accp[mp][4]), hi2(accp[mp][5]), hi2(accp[mp][6]), hi2(accp[mp][7]));
    }
}

// ---------------- split-K reduction (n = NB*C*HW fixed) ----------------
__global__ __launch_bounds__(256) void reduce_add(
    float* __restrict__ dst, const float* __restrict__ part, int S, int addto)
{
    size_t i = ((size_t)blockIdx.x * 256 + threadIdx.x) * 4;
    float4 acc;
    if (addto) acc = *(const float4*)(dst + i);
    else acc = make_float4(0.f, 0.f, 0.f, 0.f);
    for (int s = 0; s < S; s++) {
        float4 p = *(const float4*)(part + (size_t)s * (NB * C * HW) + i);
        acc.x += p.x; acc.y += p.y; acc.z += p.z; acc.w += p.w;
    }
    *(float4*)(dst + i) = acc;
}

// ---------------- layernorm over channels ----------------
__global__ __launch_bounds__(256) void ln_kernel(
    const float* __restrict__ x, const float* __restrict__ w,
    const float* __restrict__ bias, float* __restrict__ y)
{
    int b = blockIdx.y;
    int n0 = blockIdx.x * 32;
    int nx = threadIdx.x & 31;
    int cg = threadIdx.x >> 5;
    const float* xb = x + (size_t)b * C * HW + n0 + nx;

    float v[32];
    float s = 0.f, ss = 0.f;
    #pragma unroll
    for (int i = 0; i < 32; i++) {
        float t = xb[(size_t)(cg * 32 + i) * HW];
        v[i] = t; s += t; ss += t * t;
    }
    __shared__ float rs[8][32], rss[8][32];
    rs[cg][nx] = s; rss[cg][nx] = ss;
    __syncthreads();
    float tot = 0.f, tot2 = 0.f;
    #pragma unroll
    for (int g = 0; g < 8; g++) { tot += rs[g][nx]; tot2 += rss[g][nx]; }
    float mu = tot * (1.f / 256.f);
    float var = tot2 * (1.f / 256.f) - mu * mu;
    float rstd = rsqrtf(var + 1e-5f);

    float* yb = y + (size_t)b * C * HW + n0 + nx;
    #pragma unroll
    for (int i = 0; i < 32; i++) {
        int c = cg * 32 + i;
        yb[(size_t)c * HW] = (v[i] - mu) * rstd * w[c] + bias[c];
    }
}

// ---------------- fused flash attention (d=64, N=1024), f32x2 inner loops ----------------
__global__ __launch_bounds__(256) void attn64(
    const float* __restrict__ Q, const float* __restrict__ Kg,
    const float* __restrict__ V, float* __restrict__ O, size_t bstride)
{
    extern __shared__ float sm[];
    float (*Qs)[64] = (float(*)[64])(sm);
    float (*Ks)[64] = (float(*)[64])(sm + 4096);
    float (*Vs)[68] = (float(*)[68])(sm + 8192);
    float (*Ps)[68] = (float(*)[68])(sm + 8192 + 4352);

    int n0 = blockIdx.x * 64;
    size_t ib = (size_t)blockIdx.z * bstride + (size_t)blockIdx.y * 64 * HW;
    size_t ob = ((size_t)blockIdx.z * C + (size_t)blockIdx.y * 64) * (size_t)HW;
    const float* Qb = Q + ib;
    const float* Kb = Kg + ib;
    const float* Vb = V + ib;

    int tid = threadIdx.x;
    int tx = tid & 15, ty = tid >> 4;

    for (int idx = tid; idx < 4096; idx += 256) {
        int d = idx >> 6, q = idx & 63;
        Qs[d][q] = Qb[(size_t)d * HW + n0 + q];
    }

    unsigned long long op[4][2] = {};
    float mrun[4], lrun[4];
    #pragma unroll
    for (int i = 0; i < 4; i++) { mrun[i] = -1e30f; lrun[i] = 0.f; }

    for (int m0 = 0; m0 < HW; m0 += 64) {
        __syncthreads();
        for (int idx = tid; idx < 4096; idx += 256) {
            int d = idx >> 6, m = idx & 63;
            Ks[d][m] = Kb[(size_t)d * HW + m0 + m];
            Vs[m][d] = Vb[(size_t)d * HW + m0 + m];
        }
        __syncthreads();

        unsigned long long sp[4][2] = {};
        #pragma unroll 8
        for (int d = 0; d < 64; d++) {
            float4 av = *(const float4*)&Qs[d][ty << 2];
            ulonglong2 bp = *(const ulonglong2*)&Ks[d][tx << 2];
            unsigned long long a0 = pk2(av.x), a1 = pk2(av.y), a2 = pk2(av.z), a3 = pk2(av.w);
            ffma2(sp[0][0], a0, bp.x); ffma2(sp[0][1], a0, bp.y);
            ffma2(sp[1][0], a1, bp.x); ffma2(sp[1][1], a1, bp.y);
            ffma2(sp[2][0], a2, bp.x); ffma2(sp[2][1], a2, bp.y);
            ffma2(sp[3][0], a3, bp.x); ffma2(sp[3][1], a3, bp.y);
        }
        float s[4][4];
        #pragma unroll
        for (int i = 0; i < 4; i++) {
            s[i][0] = lo2(sp[i][0]) * 0.125f;
            s[i][1] = hi2(sp[i][0]) * 0.125f;
            s[i][2] = lo2(sp[i][1]) * 0.125f;
            s[i][3] = hi2(sp[i][1]) * 0.125f;
        }

        #pragma unroll
        for (int i = 0; i < 4; i++) {
            float mx = fmaxf(fmaxf(s[i][0], s[i][1]), fmaxf(s[i][2], s[i][3]));
            #pragma unroll
            for (int o = 1; o < 16; o <<= 1)
                mx = fmaxf(mx, __shfl_xor_sync(0xffffffffu, mx, o));
            float mnew = fmaxf(mrun[i], mx);
            float corr = __expf(mrun[i] - mnew);
            float rsum = 0.f;
            #pragma unroll
            for (int j = 0; j < 4; j++) {
                float p = __expf(s[i][j] - mnew);
                s[i][j] = p; rsum += p;
            }
            #pragma unroll
            for (int o = 1; o < 16; o <<= 1)
                rsum += __shfl_xor_sync(0xffffffffu, rsum, o);
            lrun[i] = lrun[i] * corr + rsum;
            mrun[i] = mnew;
            unsigned long long cp = pk2(corr);
            mul2(op[i][0], cp); mul2(op[i][1], cp);
            #pragma unroll
            for (int j = 0; j < 4; j++) Ps[(ty << 2) + i][(tx << 2) + j] = s[i][j];
        }
        __syncthreads();

        #pragma unroll 8
        for (int m = 0; m < 64; m++) {
            ulonglong2 vp = *(const ulonglong2*)&Vs[m][tx << 2];
            unsigned long long a0 = pk2(Ps[(ty << 2) + 0][m]);
            unsigned long long a1 = pk2(Ps[(ty << 2) + 1][m]);
            unsigned long long a2 = pk2(Ps[(ty << 2) + 2][m]);
            unsigned long long a3 = pk2(Ps[(ty << 2) + 3][m]);
            ffma2(op[0][0], a0, vp.x); ffma2(op[0][1], a0, vp.y);
            ffma2(op[1][0], a1, vp.x); ffma2(op[1][1], a1, vp.y);
            ffma2(op[2][0], a2, vp.x); ffma2(op[2][1], a2, vp.y);
            ffma2(op[3][0], a3, vp.x); ffma2(op[3][1], a3, vp.y);
        }
    }

    float* Ob = O + ob;
    #pragma unroll
    for (int i = 0; i < 4; i++) {
        float linv = 1.f / lrun[i];
        #pragma unroll
        for (int j = 0; j < 4; j++) {
            float v = (j & 1) ? hi2(op[i][j >> 1]) : lo2(op[i][j >> 1]);
            Ob[(size_t)((tx << 2) + j) * HW + n0 + (ty << 2) + i] = v * linv;
        }
    }
}

// ---------------- depthwise 3x3 conv + exact GELU ----------------
__global__ __launch_bounds__(256) void dwconv_gelu(
    const float* __restrict__ X, const float* __restrict__ W, float* __restrict__ Y)
{
    int idx = blockIdx.x * 256 + threadIdx.x;
    int x = idx & 31;
    int y = (idx >> 5) & 31;
    int c = (idx >> 10) & 1023;
    int b = idx >> 20;
    const float* xb = X + ((size_t)b * HIDDEN + c) * HW;
    const float* wc = W + c * 9;
    float acc = 0.f;
    #pragma unroll
    for (int dy = 0; dy < 3; dy++) {
        int iy = y + dy - 1;
        #pragma unroll
        for (int dx = 0; dx < 3; dx++) {
            int ix = x + dx - 1;
            if ((unsigned)iy < 32u && (unsigned)ix < 32u)
                acc += wc[dy * 3 + dx] * xb[(iy << 5) + ix];
        }
    }
    float g = 0.5f * acc * (1.f + erff(acc * 0.70710678118654752440f));
    Y[idx] = g;
}

// ---------------- host orchestration ----------------
extern "C" void kernel_launch(void* const* d_in, const int* in_sizes, int n_in,
                              void* d_out, int out_size)
{
    const float* aop      = (const float*)d_in[0];
    const float* dop      = (const float*)d_in[1];
    const float* w_qconv  = (const float*)d_in[2];
    const float* w_kvconv = (const float*)d_in[3];
    const float* lnq1_w   = (const float*)d_in[4];
    const float* lnq1_b   = (const float*)d_in[5];
    const float* lnkv1_w  = (const float*)d_in[6];
    const float* lnkv1_b  = (const float*)d_in[7];
    const float* lnq2_w   = (const float*)d_in[8];
    const float* lnq2_b   = (const float*)d_in[9];
    const float* lnkv2_w  = (const float*)d_in[10];
    const float* lnkv2_b  = (const float*)d_in[11];
    const float* lnffn_w  = (const float*)d_in[12];
    const float* lnffn_b  = (const float*)d_in[13];
    const float* saq_qkv  = (const float*)d_in[14];
    const float* saq_proj = (const float*)d_in[15];
    const float* sakv_qkv = (const float*)d_in[16];
    const float* sakv_proj= (const float*)d_in[17];
    const float* ca_q     = (const float*)d_in[18];
    const float* ca_k     = (const float*)d_in[19];
    const float* ca_v     = (const float*)d_in[20];
    const float* ca_proj  = (const float*)d_in[21];
    const float* leff_in  = (const float*)d_in[22];
    const float* leff_dw  = (const float*)d_in[23];
    const float* leff_out = (const float*)d_in[24];
    float* out = (float*)d_out;

    float *qbr, *kvbr, *tmp, *qb, *kb, *vb, *att, *h1, *h2;
    cudaGetSymbolAddress((void**)&qbr,  g_qbranch);
    cudaGetSymbolAddress((void**)&kvbr, g_kvbranch);
    cudaGetSymbolAddress((void**)&tmp,  g_tmp);
    cudaGetSymbolAddress((void**)&qb,   g_qb);
    cudaGetSymbolAddress((void**)&kb,   g_kb);
    cudaGetSymbolAddress((void**)&vb,   g_vb);
    cudaGetSymbolAddress((void**)&att,  g_attn);
    cudaGetSymbolAddress((void**)&h1,   g_h1);
    cudaGetSymbolAddress((void**)&h2,   g_h2);

    const int ATTN_SMEM = (4096 + 4096 + 4352 + 4352) * 4;
    cudaFuncSetAttribute(attn64, cudaFuncAttributeMaxDynamicSharedMemorySize, ATTN_SMEM);

    dim3 gC(8, 4, NB);          // M = 256
    dim3 gQKV(8, 12, NB);       // M = 768
    dim3 gHID(8, 16, NB);       // M = 1024
    dim3 gCS4(8, 4, NB * 4);    // M = 256, split-K 4
    dim3 gCS2(8, 4, NB * 2);    // M = 256, split-K 2
    dim3 gLN(32, NB);
    dim3 gATT(16, 4, NB);
    size_t strideQKV = (size_t)768 * HW;
    size_t strideC   = (size_t)C * HW;

    // ---- q branch ----
    conv_f2<3, 1><<<gCS4, 128>>>(w_qconv, aop, h1, 4);
    reduce_add<<<2048, 256>>>(qbr, h1, 4, 0);
    ln_kernel<<<gLN, 256>>>(qbr, lnq1_w, lnq1_b, tmp);
    sgemm_f2<<<gQKV, 128>>>(saq_qkv, tmp, h2, nullptr, 768, C, 1);
    attn64<<<gATT, 256, ATTN_SMEM>>>(h2, h2 + 256 * HW, h2 + 512 * HW, att, strideQKV);
    sgemm_f2<<<gC, 128>>>(saq_proj, att, qbr, qbr, C, C, 1);

    // ---- kv branch ----
    conv_f2<5, 2><<<gCS4, 128>>>(w_kvconv, dop, h1, 4);
    reduce_add<<<2048, 256>>>(kvbr, h1, 4, 0);
    ln_kernel<<<gLN, 256>>>(kvbr, lnkv1_w, lnkv1_b, tmp);
    sgemm_f2<<<gQKV, 128>>>(sakv_qkv, tmp, h2, nullptr, 768, C, 1);
    attn64<<<gATT, 256, ATTN_SMEM>>>(h2, h2 + 256 * HW, h2 + 512 * HW, att, strideQKV);
    sgemm_f2<<<gC, 128>>>(sakv_proj, att, kvbr, kvbr, C, C, 1);

    // ---- cross attention ----
    ln_kernel<<<gLN, 256>>>(qbr, lnq2_w, lnq2_b, tmp);
    sgemm_f2<<<gC, 128>>>(ca_q, tmp, qb, nullptr, C, C, 1);
    ln_kernel<<<gLN, 256>>>(kvbr, lnkv2_w, lnkv2_b, tmp);
    sgemm_f2<<<gC, 128>>>(ca_k, tmp, kb, nullptr, C, C, 1);
    sgemm_f2<<<gC, 128>>>(ca_v, tmp, vb, nullptr, C, C, 1);
    attn64<<<gATT, 256, ATTN_SMEM>>>(qb, kb, vb, att, strideC);
    sgemm_f2<<<gC, 128>>>(ca_proj, att, out, qbr, C, C, 1);

    // ---- LeFF ----
    ln_kernel<<<gLN, 256>>>(out, lnffn_w, lnffn_b, tmp);
    sgemm_f2<<<gHID, 128>>>(leff_in, tmp, h1, nullptr, HIDDEN, C, 1);
    dwconv_gelu<<<(NB * HIDDEN * HW) / 256, 256>>>(h1, leff_dw, h2);
    sgemm_f2<<<gCS2, 128>>>(leff_out, h2, h1, nullptr, C, HIDDEN, 2);
    reduce_add<<<2048, 256>>>(out, h1, 2, 1);
}

// round 7
// speedup vs baseline: 1.5047x; 1.5047x over previous
#include <cuda_runtime.h>
#include <cuda_bf16.h>
#include <math.h>
#include <stdint.h>

#define NB 8
#define C 256
#define HW 1024
#define HIDDEN 1024

__device__ float g_qbranch[NB*C*HW];
__device__ float g_kvbranch[NB*C*HW];
__device__ float g_tmp[NB*C*HW];
__device__ float g_qb[NB*C*HW];
__device__ float g_kb[NB*C*HW];
__device__ float g_vb[NB*C*HW];
__device__ float g_attn[NB*C*HW];
__device__ float g_h1[NB*HIDDEN*HW];
__device__ float g_h2[NB*HIDDEN*HW];
__device__ __align__(256) __nv_bfloat16 g_wbf[7100000];

// weight plane offsets (hi at off, lo at off+size)
#define OC3    0ull
#define SZ3    589824ull
#define OC5    1179648ull
#define SZ5    1638400ull
#define OSAQ   4456448ull
#define SZQKV  196608ull
#define OSAKV  4849664ull
#define OSAQP  5242880ull
#define SZCC   65536ull
#define OSAKVP 5373952ull
#define OCAQ   5505024ull
#define OCAK   5636096ull
#define OCAV   5767168ull
#define OCAP   5898240ull
#define OLIN   6029312ull
#define SZLF   262144ull
#define OLOUT  6553600ull

// ---------------- helpers ----------------
__device__ __forceinline__ uint32_t smem_u32(const void* p) {
    uint32_t a;
    asm("{ .reg .u64 t; cvta.to.shared.u64 t, %1; cvt.u32.u64 %0, t; }" : "=r"(a) : "l"(p));
    return a;
}
__device__ __forceinline__ void cp16(void* dst, const void* src) {
    unsigned d = (unsigned)__cvta_generic_to_shared(dst);
    asm volatile("cp.async.ca.shared.global [%0], [%1], 16;" :: "r"(d), "l"(src));
}
__device__ __forceinline__ void cp_commit() { asm volatile("cp.async.commit_group;" ::: "memory"); }
__device__ __forceinline__ void cp_wait0()  { asm volatile("cp.async.wait_group 0;" ::: "memory"); }

__device__ __forceinline__ void ldmx4(uint32_t* r, uint32_t addr) {
    asm volatile("ldmatrix.sync.aligned.m8n8.x4.shared.b16 {%0,%1,%2,%3}, [%4];"
        : "=r"(r[0]), "=r"(r[1]), "=r"(r[2]), "=r"(r[3]) : "r"(addr));
}
__device__ __forceinline__ void mma16816(float* c, const uint32_t* a, const uint32_t* b) {
    asm volatile("mma.sync.aligned.m16n8k16.row.col.f32.bf16.bf16.f32 "
        "{%0,%1,%2,%3}, {%4,%5,%6,%7}, {%8,%9}, {%0,%1,%2,%3};"
        : "+f"(c[0]), "+f"(c[1]), "+f"(c[2]), "+f"(c[3])
        : "r"(a[0]), "r"(a[1]), "r"(a[2]), "r"(a[3]), "r"(b[0]), "r"(b[1]));
}
__device__ __forceinline__ unsigned pkbf(float a, float b) {
    __nv_bfloat16 ha = __float2bfloat16(a), hb = __float2bfloat16(b);
    return ((unsigned)__bfloat16_as_ushort(hb) << 16) | __bfloat16_as_ushort(ha);
}

// f32x2 (attention)
__device__ __forceinline__ void ffma2(unsigned long long& d, unsigned long long a, unsigned long long b) {
    asm("fma.rn.f32x2 %0, %1, %2, %0;" : "+l"(d) : "l"(a), "l"(b));
}
__device__ __forceinline__ void mul2(unsigned long long& d, unsigned long long a) {
    asm("mul.rn.f32x2 %0, %0, %1;" : "+l"(d) : "l"(a));
}
__device__ __forceinline__ unsigned long long pk2(float x) {
    unsigned u = __float_as_uint(x);
    unsigned long long r;
    asm("mov.b64 %0, {%1, %1};" : "=l"(r) : "r"(u));
    return r;
}
__device__ __forceinline__ float lo2(unsigned long long v){ return __uint_as_float((unsigned)v); }
__device__ __forceinline__ float hi2(unsigned long long v){ return __uint_as_float((unsigned)(v >> 32)); }

// =====================================================================
// mma.sync GEMM / implicit conv. act channel-major [b][SA][1024].
// out[(b*Cout+oc)*1024+pix] = sum_k act * W[oc][k]  (+ addp, same layout)
// grid (8 pixtiles, Cout/128, NB), 256 threads, dyn smem 131072
// smem stage (65536B): AH 16K | AL 16K | BH 16K | BL 16K
// A/B tiles [row 0..127][k-group g 0..7], 16B unit at row*128 + ((g^(row&7))*16)
// =====================================================================
template<int KW, int PAD>
__global__ __launch_bounds__(256, 1) void mm_tc(
    const __nv_bfloat16* __restrict__ whi, const __nv_bfloat16* __restrict__ wlo,
    const float* __restrict__ act, float* __restrict__ outp,
    const float* __restrict__ addp, int K, int SA, int Cout)
{
    extern __shared__ char sm[];
    int tid = threadIdx.x;
    int pixbase = blockIdx.x * 128;
    int ocbase = blockIdx.y * 128;
    int bimg = blockIdx.z;
    int w = tid >> 5, lane = tid & 31;
    int m0 = (w >> 1) * 32;     // warp pixel base (4 warps)
    int n0 = (w & 1) * 64;      // warp oc base (2 warps)
    uint32_t sbase = smem_u32(sm);

    float acc[2][8][4] = {};

    int apix = tid & 127, ahalf = tid >> 7;

    auto fetchA = [&](int kk, float* v) {
        if (KW == 0) {
            const float* p = act + ((size_t)bimg * SA + kk + ahalf * 32) * 1024 + pixbase + apix;
            #pragma unroll
            for (int i = 0; i < 32; i++) v[i] = p[(size_t)i * 1024];
        } else {
            int kbase = kk + ahalf * 32;
            int tap = kbase >> 8, ic0 = kbase & 255;
            int dy = tap / KW - PAD, dx = tap % KW - PAD;
            int p = pixbase + apix;
            int iy = (p >> 5) + dy, ix = (p & 31) + dx;
            bool ok = ((unsigned)iy < 32u) && ((unsigned)ix < 32u);
            const float* src = act + ((size_t)bimg * 256 + ic0) * 1024 + (iy << 5) + ix;
            #pragma unroll
            for (int i = 0; i < 32; i++) v[i] = ok ? src[(size_t)i * 1024] : 0.f;
        }
    };
    auto storeA = [&](int st, const float* v) {
        char* AH = sm + st * 65536;
        char* AL = AH + 16384;
        #pragma unroll
        for (int gi = 0; gi < 4; gi++) {
            int g = ahalf * 4 + gi;
            unsigned hh[4], ll[4];
            #pragma unroll
            for (int m = 0; m < 4; m++) {
                float a = v[gi * 8 + 2 * m], b = v[gi * 8 + 2 * m + 1];
                __nv_bfloat16 ha = __float2bfloat16(a), hb = __float2bfloat16(b);
                hh[m] = ((unsigned)__bfloat16_as_ushort(hb) << 16) | __bfloat16_as_ushort(ha);
                ll[m] = pkbf(a - __bfloat162float(ha), b - __bfloat162float(hb));
            }
            unsigned off = apix * 128 + ((g ^ (apix & 7)) << 4);
            *(uint4*)(AH + off) = make_uint4(hh[0], hh[1], hh[2], hh[3]);
            *(uint4*)(AL + off) = make_uint4(ll[0], ll[1], ll[2], ll[3]);
        }
    };
    auto loadB = [&](int st, int kk) {
        char* base = sm + st * 65536 + 32768;
        #pragma unroll
        for (int i = 0; i < 8; i++) {
            int idx = tid + i * 256;
            int plane = idx >> 10, r = idx & 1023;
            int oc = r >> 3, g = r & 7;
            const __nv_bfloat16* src = (plane ? wlo : whi) + (size_t)(ocbase + oc) * K + kk + g * 8;
            unsigned off = oc * 128 + ((g ^ (oc & 7)) << 4);
            cp16(base + plane * 16384 + off, src);
        }
    };
    auto compute = [&](int st) {
        uint32_t AH = sbase + st * 65536, AL = AH + 16384;
        uint32_t BH = AH + 32768, BL = AH + 49152;
        #pragma unroll
        for (int ks = 0; ks < 4; ks++) {
            int kg = ks * 2;
            uint32_t aH[2][4], aL[2][4], bH[8][2], bL[8][2];
            #pragma unroll
            for (int ms = 0; ms < 2; ms++) {
                int sel = lane >> 3;
                int row = m0 + ms * 16 + (sel & 1) * 8 + (lane & 7);
                int g = kg + (sel >> 1);
                unsigned off = row * 128 + ((g ^ (row & 7)) << 4);
                ldmx4(aH[ms], AH + off);
                ldmx4(aL[ms], AL + off);
            }
            #pragma unroll
            for (int nj = 0; nj < 4; nj++) {
                int j2 = lane >> 4, half = (lane >> 3) & 1;
                int oc = n0 + (nj * 2 + j2) * 8 + (lane & 7);
                int g = kg + half;
                unsigned off = oc * 128 + ((g ^ (oc & 7)) << 4);
                uint32_t t[4];
                ldmx4(t, BH + off);
                bH[nj*2][0] = t[0]; bH[nj*2][1] = t[1]; bH[nj*2+1][0] = t[2]; bH[nj*2+1][1] = t[3];
                ldmx4(t, BL + off);
                bL[nj*2][0] = t[0]; bL[nj*2][1] = t[1]; bL[nj*2+1][0] = t[2]; bL[nj*2+1][1] = t[3];
            }
            #pragma unroll
            for (int ms = 0; ms < 2; ms++)
                #pragma unroll
                for (int ns = 0; ns < 8; ns++) {
                    mma16816(acc[ms][ns], aH[ms], bH[ns]);
                    mma16816(acc[ms][ns], aH[ms], bL[ns]);
                    mma16816(acc[ms][ns], aL[ms], bH[ns]);
                }
        }
    };

    // prologue
    float v[32];
    loadB(0, 0); cp_commit();
    fetchA(0, v); storeA(0, v);
    cp_wait0();
    __syncthreads();

    int nk = K >> 6;
    for (int kt = 0; kt < nk; kt++) {
        int st = kt & 1;
        bool more = (kt + 1) < nk;
        if (more) {
            loadB(st ^ 1, (kt + 1) << 6); cp_commit();
            fetchA((kt + 1) << 6, v);
        }
        compute(st);
        if (more) {
            storeA(st ^ 1, v);
            cp_wait0();
        }
        __syncthreads();
    }

    // epilogue: regs -> smem transpose -> coalesced channel-major store
    float* T = (float*)sm;   // [128 oc][132]
    #pragma unroll
    for (int ms = 0; ms < 2; ms++)
        #pragma unroll
        for (int ns = 0; ns < 8; ns++)
            #pragma unroll
            for (int e = 0; e < 4; e++) {
                int pix = m0 + ms * 16 + (lane >> 2) + (e >> 1) * 8;
                int oc  = n0 + ns * 8 + (lane & 3) * 2 + (e & 1);
                T[oc * 132 + pix] = acc[ms][ns][e];
            }
    __syncthreads();
    #pragma unroll
    for (int it = 0; it < 16; it++) {
        int f = it * 256 + tid;
        int oc = f >> 5, p4 = (f & 31) * 4;
        float4 vv = *(float4*)&T[oc * 132 + p4];
        size_t go = ((size_t)bimg * Cout + ocbase + oc) * 1024 + pixbase + p4;
        if (addp) {
            float4 a = *(const float4*)(addp + go);
            vv.x += a.x; vv.y += a.y; vv.z += a.z; vv.w += a.w;
        }
        *(float4*)(outp + go) = vv;
    }
}

// ---------------- weight prep ----------------
__global__ __launch_bounds__(256) void cvt_w(
    __nv_bfloat16* __restrict__ hi, __nv_bfloat16* __restrict__ lo,
    const float* __restrict__ s, int n)
{
    int i = blockIdx.x * 256 + threadIdx.x;
    if (i < n) {
        float v = s[i];
        __nv_bfloat16 h = __float2bfloat16(v);
        hi[i] = h;
        lo[i] = __float2bfloat16(v - __bfloat162float(h));
    }
}
// conv [oc][ic][KK] -> [oc][tap][ic]
__global__ __launch_bounds__(256) void cvt_conv_w(
    __nv_bfloat16* __restrict__ hi, __nv_bfloat16* __restrict__ lo,
    const float* __restrict__ s, int KK, int n)
{
    int i = blockIdx.x * 256 + threadIdx.x;
    if (i < n) {
        int oc = i / (KK * 256);
        int r = i - oc * KK * 256;
        int tap = r >> 8, ic = r & 255;
        float v = s[((size_t)(oc * 256 + ic)) * KK + tap];
        __nv_bfloat16 h = __float2bfloat16(v);
        hi[i] = h;
        lo[i] = __float2bfloat16(v - __bfloat162float(h));
    }
}

// ---------------- layernorm over channels (NCHW) ----------------
__global__ __launch_bounds__(256) void ln_kernel(
    const float* __restrict__ x, const float* __restrict__ w,
    const float* __restrict__ bias, float* __restrict__ y)
{
    int b = blockIdx.y;
    int n0 = blockIdx.x * 32;
    int nx = threadIdx.x & 31;
    int cg = threadIdx.x >> 5;
    const float* xb = x + (size_t)b * C * HW + n0 + nx;
    float v[32];
    float s = 0.f, ss = 0.f;
    #pragma unroll
    for (int i = 0; i < 32; i++) {
        float t = xb[(size_t)(cg * 32 + i) * HW];
        v[i] = t; s += t; ss += t * t;
    }
    __shared__ float rs[8][32], rss[8][32];
    rs[cg][nx] = s; rss[cg][nx] = ss;
    __syncthreads();
    float tot = 0.f, tot2 = 0.f;
    #pragma unroll
    for (int g = 0; g < 8; g++) { tot += rs[g][nx]; tot2 += rss[g][nx]; }
    float mu = tot * (1.f / 256.f);
    float var = tot2 * (1.f / 256.f) - mu * mu;
    float rstd = rsqrtf(var + 1e-5f);
    float* yb = y + (size_t)b * C * HW + n0 + nx;
    #pragma unroll
    for (int i = 0; i < 32; i++) {
        int c = cg * 32 + i;
        yb[(size_t)c * HW] = (v[i] - mu) * rstd * w[c] + bias[c];
    }
}

// ---------------- flash attention (d=64, N=1024), f32x2 ----------------
__global__ __launch_bounds__(256) void attn64(
    const float* __restrict__ Q, const float* __restrict__ Kg,
    const float* __restrict__ V, float* __restrict__ O, size_t bstride)
{
    extern __shared__ float smf[];
    float (*Qs)[64] = (float(*)[64])(smf);
    float (*Ks)[64] = (float(*)[64])(smf + 4096);
    float (*Vs)[68] = (float(*)[68])(smf + 8192);
    float (*Ps)[68] = (float(*)[68])(smf + 8192 + 4352);

    int n0 = blockIdx.x * 64;
    size_t ib = (size_t)blockIdx.z * bstride + (size_t)blockIdx.y * 64 * HW;
    size_t ob = ((size_t)blockIdx.z * C + (size_t)blockIdx.y * 64) * (size_t)HW;
    const float* Qb = Q + ib;
    const float* Kb = Kg + ib;
    const float* Vb = V + ib;

    int tid = threadIdx.x;
    int tx = tid & 15, ty = tid >> 4;

    for (int idx = tid; idx < 4096; idx += 256) {
        int d = idx >> 6, q = idx & 63;
        Qs[d][q] = Qb[(size_t)d * HW + n0 + q];
    }

    unsigned long long op[4][2] = {};
    float mrun[4], lrun[4];
    #pragma unroll
    for (int i = 0; i < 4; i++) { mrun[i] = -1e30f; lrun[i] = 0.f; }

    for (int m0 = 0; m0 < HW; m0 += 64) {
        __syncthreads();
        for (int idx = tid; idx < 4096; idx += 256) {
            int d = idx >> 6, m = idx & 63;
            Ks[d][m] = Kb[(size_t)d * HW + m0 + m];
            Vs[m][d] = Vb[(size_t)d * HW + m0 + m];
        }
        __syncthreads();

        unsigned long long sp[4][2] = {};
        #pragma unroll 8
        for (int d = 0; d < 64; d++) {
            float4 av = *(const float4*)&Qs[d][ty << 2];
            ulonglong2 bp = *(const ulonglong2*)&Ks[d][tx << 2];
            unsigned long long a0 = pk2(av.x), a1 = pk2(av.y), a2 = pk2(av.z), a3 = pk2(av.w);
            ffma2(sp[0][0], a0, bp.x); ffma2(sp[0][1], a0, bp.y);
            ffma2(sp[1][0], a1, bp.x); ffma2(sp[1][1], a1, bp.y);
            ffma2(sp[2][0], a2, bp.x); ffma2(sp[2][1], a2, bp.y);
            ffma2(sp[3][0], a3, bp.x); ffma2(sp[3][1], a3, bp.y);
        }
        float s[4][4];
        #pragma unroll
        for (int i = 0; i < 4; i++) {
            s[i][0] = lo2(sp[i][0]) * 0.125f;
            s[i][1] = hi2(sp[i][0]) * 0.125f;
            s[i][2] = lo2(sp[i][1]) * 0.125f;
            s[i][3] = hi2(sp[i][1]) * 0.125f;
        }
        #pragma unroll
        for (int i = 0; i < 4; i++) {
            float mx = fmaxf(fmaxf(s[i][0], s[i][1]), fmaxf(s[i][2], s[i][3]));
            #pragma unroll
            for (int o = 1; o < 16; o <<= 1)
                mx = fmaxf(mx, __shfl_xor_sync(0xffffffffu, mx, o));
            float mnew = fmaxf(mrun[i], mx);
            float corr = __expf(mrun[i] - mnew);
            float rsum = 0.f;
            #pragma unroll
            for (int j = 0; j < 4; j++) {
                float p = __expf(s[i][j] - mnew);
                s[i][j] = p; rsum += p;
            }
            #pragma unroll
            for (int o = 1; o < 16; o <<= 1)
                rsum += __shfl_xor_sync(0xffffffffu, rsum, o);
            lrun[i] = lrun[i] * corr + rsum;
            mrun[i] = mnew;
            unsigned long long cp = pk2(corr);
            mul2(op[i][0], cp); mul2(op[i][1], cp);
            #pragma unroll
            for (int j = 0; j < 4; j++) Ps[(ty << 2) + i][(tx << 2) + j] = s[i][j];
        }
        __syncthreads();
        #pragma unroll 8
        for (int m = 0; m < 64; m++) {
            ulonglong2 vp = *(const ulonglong2*)&Vs[m][tx << 2];
            unsigned long long a0 = pk2(Ps[(ty << 2) + 0][m]);
            unsigned long long a1 = pk2(Ps[(ty << 2) + 1][m]);
            unsigned long long a2 = pk2(Ps[(ty << 2) + 2][m]);
            unsigned long long a3 = pk2(Ps[(ty << 2) + 3][m]);
            ffma2(op[0][0], a0, vp.x); ffma2(op[0][1], a0, vp.y);
            ffma2(op[1][0], a1, vp.x); ffma2(op[1][1], a1, vp.y);
            ffma2(op[2][0], a2, vp.x); ffma2(op[2][1], a2, vp.y);
            ffma2(op[3][0], a3, vp.x); ffma2(op[3][1], a3, vp.y);
        }
    }

    float* Ob = O + ob;
    #pragma unroll
    for (int i = 0; i < 4; i++) {
        float linv = 1.f / lrun[i];
        #pragma unroll
        for (int j = 0; j < 4; j++) {
            float vv = (j & 1) ? hi2(op[i][j >> 1]) : lo2(op[i][j >> 1]);
            Ob[(size_t)((tx << 2) + j) * HW + n0 + (ty << 2) + i] = vv * linv;
        }
    }
}

// ---------------- depthwise 3x3 + exact GELU ----------------
__global__ __launch_bounds__(256) void dwconv_gelu(
    const float* __restrict__ X, const float* __restrict__ W, float* __restrict__ Y)
{
    int idx = blockIdx.x * 256 + threadIdx.x;
    int x = idx & 31;
    int y = (idx >> 5) & 31;
    int c = (idx >> 10) & 1023;
    int b = idx >> 20;
    const float* xb = X + ((size_t)b * HIDDEN + c) * HW;
    const float* wc = W + c * 9;
    float acc = 0.f;
    #pragma unroll
    for (int dy = 0; dy < 3; dy++) {
        int iy = y + dy - 1;
        #pragma unroll
        for (int dx = 0; dx < 3; dx++) {
            int ix = x + dx - 1;
            if ((unsigned)iy < 32u && (unsigned)ix < 32u)
                acc += wc[dy * 3 + dx] * xb[(iy << 5) + ix];
        }
    }
    Y[idx] = 0.5f * acc * (1.f + erff(acc * 0.70710678118654752440f));
}

// ---------------- host ----------------
extern "C" void kernel_launch(void* const* d_in, const int* in_sizes, int n_in,
                              void* d_out, int out_size)
{
    const float* aop      = (const float*)d_in[0];
    const float* dop      = (const float*)d_in[1];
    const float* w_qconv  = (const float*)d_in[2];
    const float* w_kvconv = (const float*)d_in[3];
    const float* lnq1_w   = (const float*)d_in[4];
    const float* lnq1_b   = (const float*)d_in[5];
    const float* lnkv1_w  = (const float*)d_in[6];
    const float* lnkv1_b  = (const float*)d_in[7];
    const float* lnq2_w   = (const float*)d_in[8];
    const float* lnq2_b   = (const float*)d_in[9];
    const float* lnkv2_w  = (const float*)d_in[10];
    const float* lnkv2_b  = (const float*)d_in[11];
    const float* lnffn_w  = (const float*)d_in[12];
    const float* lnffn_b  = (const float*)d_in[13];
    const float* saq_qkv  = (const float*)d_in[14];
    const float* saq_proj = (const float*)d_in[15];
    const float* sakv_qkv = (const float*)d_in[16];
    const float* sakv_proj= (const float*)d_in[17];
    const float* ca_q     = (const float*)d_in[18];
    const float* ca_k     = (const float*)d_in[19];
    const float* ca_v     = (const float*)d_in[20];
    const float* ca_proj  = (const float*)d_in[21];
    const float* leff_in  = (const float*)d_in[22];
    const float* leff_dw  = (const float*)d_in[23];
    const float* leff_out = (const float*)d_in[24];
    float* out = (float*)d_out;

    float *qbr, *kvbr, *tmp, *qb, *kb, *vb, *att, *h1, *h2;
    __nv_bfloat16* wbf;
    cudaGetSymbolAddress((void**)&qbr,  g_qbranch);
    cudaGetSymbolAddress((void**)&kvbr, g_kvbranch);
    cudaGetSymbolAddress((void**)&tmp,  g_tmp);
    cudaGetSymbolAddress((void**)&qb,   g_qb);
    cudaGetSymbolAddress((void**)&kb,   g_kb);
    cudaGetSymbolAddress((void**)&vb,   g_vb);
    cudaGetSymbolAddress((void**)&att,  g_attn);
    cudaGetSymbolAddress((void**)&h1,   g_h1);
    cudaGetSymbolAddress((void**)&h2,   g_h2);
    cudaGetSymbolAddress((void**)&wbf,  g_wbf);

    const int ATTN_SMEM = (4096 + 4096 + 4352 + 4352) * 4;
    const int MM_SMEM = 131072;
    cudaFuncSetAttribute(attn64, cudaFuncAttributeMaxDynamicSharedMemorySize, ATTN_SMEM);
    cudaFuncSetAttribute(mm_tc<0,0>, cudaFuncAttributeMaxDynamicSharedMemorySize, MM_SMEM);
    cudaFuncSetAttribute(mm_tc<3,1>, cudaFuncAttributeMaxDynamicSharedMemorySize, MM_SMEM);
    cudaFuncSetAttribute(mm_tc<5,2>, cudaFuncAttributeMaxDynamicSharedMemorySize, MM_SMEM);

    // weight prep
    cvt_conv_w<<<(int)((SZ3+255)/256), 256>>>(wbf+OC3, wbf+OC3+SZ3, w_qconv, 9, (int)SZ3);
    cvt_conv_w<<<(int)((SZ5+255)/256), 256>>>(wbf+OC5, wbf+OC5+SZ5, w_kvconv, 25, (int)SZ5);
    cvt_w<<<(int)((SZQKV+255)/256), 256>>>(wbf+OSAQ,  wbf+OSAQ+SZQKV,  saq_qkv,  (int)SZQKV);
    cvt_w<<<(int)((SZQKV+255)/256), 256>>>(wbf+OSAKV, wbf+OSAKV+SZQKV, sakv_qkv, (int)SZQKV);
    cvt_w<<<(int)((SZCC+255)/256), 256>>>(wbf+OSAQP,  wbf+OSAQP+SZCC,  saq_proj, (int)SZCC);
    cvt_w<<<(int)((SZCC+255)/256), 256>>>(wbf+OSAKVP, wbf+OSAKVP+SZCC, sakv_proj,(int)SZCC);
    cvt_w<<<(int)((SZCC+255)/256), 256>>>(wbf+OCAQ, wbf+OCAQ+SZCC, ca_q, (int)SZCC);
    cvt_w<<<(int)((SZCC+255)/256), 256>>>(wbf+OCAK, wbf+OCAK+SZCC, ca_k, (int)SZCC);
    cvt_w<<<(int)((SZCC+255)/256), 256>>>(wbf+OCAV, wbf+OCAV+SZCC, ca_v, (int)SZCC);
    cvt_w<<<(int)((SZCC+255)/256), 256>>>(wbf+OCAP, wbf+OCAP+SZCC, ca_proj, (int)SZCC);
    cvt_w<<<(int)((SZLF+255)/256), 256>>>(wbf+OLIN,  wbf+OLIN+SZLF,  leff_in,  (int)SZLF);
    cvt_w<<<(int)((SZLF+255)/256), 256>>>(wbf+OLOUT, wbf+OLOUT+SZLF, leff_out, (int)SZLF);

    dim3 gC(8, 2, NB), gQKV(8, 6, NB), gHID(8, 8, NB);
    dim3 gLN(32, NB), gATT(16, 4, NB);
    size_t strideQKV = (size_t)768 * HW;
    size_t strideC = (size_t)C * HW;

    // ---- q branch ----
    mm_tc<3,1><<<gC, 256, MM_SMEM>>>(wbf+OC3, wbf+OC3+SZ3, aop, qbr, nullptr, 2304, 256, 256);
    ln_kernel<<<gLN, 256>>>(qbr, lnq1_w, lnq1_b, tmp);
    mm_tc<0,0><<<gQKV, 256, MM_SMEM>>>(wbf+OSAQ, wbf+OSAQ+SZQKV, tmp, h2, nullptr, 256, 256, 768);
    attn64<<<gATT, 256, ATTN_SMEM>>>(h2, h2 + 256 * HW, h2 + 512 * HW, att, strideQKV);
    mm_tc<0,0><<<gC, 256, MM_SMEM>>>(wbf+OSAQP, wbf+OSAQP+SZCC, att, qbr, qbr, 256, 256, 256);

    // ---- kv branch ----
    mm_tc<5,2><<<gC, 256, MM_SMEM>>>(wbf+OC5, wbf+OC5+SZ5, dop, kvbr, nullptr, 6400, 256, 256);
    ln_kernel<<<gLN, 256>>>(kvbr, lnkv1_w, lnkv1_b, tmp);
    mm_tc<0,0><<<gQKV, 256, MM_SMEM>>>(wbf+OSAKV, wbf+OSAKV+SZQKV, tmp, h2, nullptr, 256, 256, 768);
    attn64<<<gATT, 256, ATTN_SMEM>>>(h2, h2 + 256 * HW, h2 + 512 * HW, att, strideQKV);
    mm_tc<0,0><<<gC, 256, MM_SMEM>>>(wbf+OSAKVP, wbf+OSAKVP+SZCC, att, kvbr, kvbr, 256, 256, 256);

    // ---- cross attention ----
    ln_kernel<<<gLN, 256>>>(qbr, lnq2_w, lnq2_b, tmp);
    mm_tc<0,0><<<gC, 256, MM_SMEM>>>(wbf+OCAQ, wbf+OCAQ+SZCC, tmp, qb, nullptr, 256, 256, 256);
    ln_kernel<<<gLN, 256>>>(kvbr, lnkv2_w, lnkv2_b, tmp);
    mm_tc<0,0><<<gC, 256, MM_SMEM>>>(wbf+OCAK, wbf+OCAK+SZCC, tmp, kb, nullptr, 256, 256, 256);
    mm_tc<0,0><<<gC, 256, MM_SMEM>>>(wbf+OCAV, wbf+OCAV+SZCC, tmp, vb, nullptr, 256, 256, 256);
    attn64<<<gATT, 256, ATTN_SMEM>>>(qb, kb, vb, att, strideC);
    mm_tc<0,0><<<gC, 256, MM_SMEM>>>(wbf+OCAP, wbf+OCAP+SZCC, att, out, qbr, 256, 256, 256);

    // ---- LeFF ----
    ln_kernel<<<gLN, 256>>>(out, lnffn_w, lnffn_b, tmp);
    mm_tc<0,0><<<gHID, 256, MM_SMEM>>>(wbf+OLIN, wbf+OLIN+SZLF, tmp, h1, nullptr, 256, 256, 1024);
    dwconv_gelu<<<(NB * HIDDEN * HW) / 256, 256>>>(h1, leff_dw, h2);
    mm_tc<0,0><<<gC, 256, MM_SMEM>>>(wbf+OLOUT, wbf+OLOUT+SZLF, h2, out, out, 1024, 1024, 256);
}

// round 8
// speedup vs baseline: 2.0433x; 1.3579x over previous
#include <cuda_runtime.h>
#include <cuda_bf16.h>
#include <math.h>
#include <stdint.h>

#define NB 8
#define C 256
#define HW 1024
#define HIDDEN 1024

__device__ float g_qbranch[NB*C*HW];
__device__ float g_kvbranch[NB*C*HW];
__device__ float g_tmp[NB*C*HW];
__device__ float g_qb[NB*C*HW];
__device__ float g_kb[NB*C*HW];
__device__ float g_vb[NB*C*HW];
__device__ float g_attn[NB*C*HW];
__device__ float g_h1[NB*HIDDEN*HW];
__device__ float g_h2[NB*HIDDEN*HW];
__device__ __align__(256) __nv_bfloat16 g_wbf[7100000];

#define OC3    0ull
#define SZ3    589824ull
#define OC5    1179648ull
#define SZ5    1638400ull
#define OSAQ   4456448ull
#define SZQKV  196608ull
#define OSAKV  4849664ull
#define OSAQP  5242880ull
#define SZCC   65536ull
#define OSAKVP 5373952ull
#define OCAQ   5505024ull
#define OCAK   5636096ull
#define OCAV   5767168ull
#define OCAP   5898240ull
#define OLIN   6029312ull
#define SZLF   262144ull
#define OLOUT  6553600ull

// ---------------- helpers ----------------
__device__ __forceinline__ uint32_t smem_u32(const void* p) {
    uint32_t a;
    asm("{ .reg .u64 t; cvta.to.shared.u64 t, %1; cvt.u32.u64 %0, t; }" : "=r"(a) : "l"(p));
    return a;
}
__device__ __forceinline__ void cp16(void* dst, const void* src) {
    unsigned d = (unsigned)__cvta_generic_to_shared(dst);
    asm volatile("cp.async.ca.shared.global [%0], [%1], 16;" :: "r"(d), "l"(src));
}
__device__ __forceinline__ void cp_commit() { asm volatile("cp.async.commit_group;" ::: "memory"); }
__device__ __forceinline__ void cp_wait0()  { asm volatile("cp.async.wait_group 0;" ::: "memory"); }

__device__ __forceinline__ void ldmx4(uint32_t* r, uint32_t addr) {
    asm volatile("ldmatrix.sync.aligned.m8n8.x4.shared.b16 {%0,%1,%2,%3}, [%4];"
        : "=r"(r[0]), "=r"(r[1]), "=r"(r[2]), "=r"(r[3]) : "r"(addr));
}
__device__ __forceinline__ void mma16816(float* c, const uint32_t* a, const uint32_t* b) {
    asm volatile("mma.sync.aligned.m16n8k16.row.col.f32.bf16.bf16.f32 "
        "{%0,%1,%2,%3}, {%4,%5,%6,%7}, {%8,%9}, {%0,%1,%2,%3};"
        : "+f"(c[0]), "+f"(c[1]), "+f"(c[2]), "+f"(c[3])
        : "r"(a[0]), "r"(a[1]), "r"(a[2]), "r"(a[3]), "r"(b[0]), "r"(b[1]));
}
__device__ __forceinline__ unsigned pkbf(float a, float b) {
    __nv_bfloat16 ha = __float2bfloat16(a), hb = __float2bfloat16(b);
    return ((unsigned)__bfloat16_as_ushort(hb) << 16) | __bfloat16_as_ushort(ha);
}
__device__ __forceinline__ void splitpk(float a, float b, unsigned& hi, unsigned& lo) {
    __nv_bfloat16 ha = __float2bfloat16(a), hb = __float2bfloat16(b);
    hi = ((unsigned)__bfloat16_as_ushort(hb) << 16) | __bfloat16_as_ushort(ha);
    lo = pkbf(a - __bfloat162float(ha), b - __bfloat162float(hb));
}

// =====================================================================
// mma.sync GEMM / implicit conv. act channel-major [b][SA][1024].
// tokmaj=0: out[(b*Cout+oc)*1024+pix] (+addp). tokmaj=1: out[(b*1024+pix)*Cout+oc]
// grid (8 pixtiles, Cout/128, NB), 256 threads, dyn smem 131072
// =====================================================================
template<int KW, int PAD>
__global__ __launch_bounds__(256, 1) void mm_tc(
    const __nv_bfloat16* __restrict__ whi, const __nv_bfloat16* __restrict__ wlo,
    const float* __restrict__ act, float* __restrict__ outp,
    const float* __restrict__ addp, int K, int SA, int Cout, int tokmaj)
{
    extern __shared__ char sm[];
    int tid = threadIdx.x;
    int pixbase = blockIdx.x * 128;
    int ocbase = blockIdx.y * 128;
    int bimg = blockIdx.z;
    int w = tid >> 5, lane = tid & 31;
    int m0 = (w >> 1) * 32;
    int n0 = (w & 1) * 64;
    uint32_t sbase = smem_u32(sm);

    float acc[2][8][4] = {};
    int apix = tid & 127, ahalf = tid >> 7;

    auto fetchA = [&](int kk, float* v) {
        if (KW == 0) {
            const float* p = act + ((size_t)bimg * SA + kk + ahalf * 32) * 1024 + pixbase + apix;
            #pragma unroll
            for (int i = 0; i < 32; i++) v[i] = p[(size_t)i * 1024];
        } else {
            int kbase = kk + ahalf * 32;
            int tap = kbase >> 8, ic0 = kbase & 255;
            int dy = tap / KW - PAD, dx = tap % KW - PAD;
            int p = pixbase + apix;
            int iy = (p >> 5) + dy, ix = (p & 31) + dx;
            bool ok = ((unsigned)iy < 32u) && ((unsigned)ix < 32u);
            const float* src = act + ((size_t)bimg * 256 + ic0) * 1024 + (iy << 5) + ix;
            #pragma unroll
            for (int i = 0; i < 32; i++) v[i] = ok ? src[(size_t)i * 1024] : 0.f;
        }
    };
    auto storeA = [&](int st, const float* v) {
        char* AH = sm + st * 65536;
        char* AL = AH + 16384;
        #pragma unroll
        for (int gi = 0; gi < 4; gi++) {
            int g = ahalf * 4 + gi;
            unsigned hh[4], ll[4];
            #pragma unroll
            for (int m = 0; m < 4; m++)
                splitpk(v[gi * 8 + 2 * m], v[gi * 8 + 2 * m + 1], hh[m], ll[m]);
            unsigned off = apix * 128 + ((g ^ (apix & 7)) << 4);
            *(uint4*)(AH + off) = make_uint4(hh[0], hh[1], hh[2], hh[3]);
            *(uint4*)(AL + off) = make_uint4(ll[0], ll[1], ll[2], ll[3]);
        }
    };
    auto loadB = [&](int st, int kk) {
        char* base = sm + st * 65536 + 32768;
        #pragma unroll
        for (int i = 0; i < 8; i++) {
            int idx = tid + i * 256;
            int plane = idx >> 10, r = idx & 1023;
            int oc = r >> 3, g = r & 7;
            const __nv_bfloat16* src = (plane ? wlo : whi) + (size_t)(ocbase + oc) * K + kk + g * 8;
            unsigned off = oc * 128 + ((g ^ (oc & 7)) << 4);
            cp16(base + plane * 16384 + off, src);
        }
    };
    auto compute = [&](int st) {
        uint32_t AH = sbase + st * 65536, AL = AH + 16384;
        uint32_t BH = AH + 32768, BL = AH + 49152;
        #pragma unroll
        for (int ks = 0; ks < 4; ks++) {
            int kg = ks * 2;
            uint32_t aH[2][4], aL[2][4], bH[8][2], bL[8][2];
            #pragma unroll
            for (int ms = 0; ms < 2; ms++) {
                int sel = lane >> 3;
                int row = m0 + ms * 16 + (sel & 1) * 8 + (lane & 7);
                int g = kg + (sel >> 1);
                unsigned off = row * 128 + ((g ^ (row & 7)) << 4);
                ldmx4(aH[ms], AH + off);
                ldmx4(aL[ms], AL + off);
            }
            #pragma unroll
            for (int nj = 0; nj < 4; nj++) {
                int j2 = lane >> 4, half = (lane >> 3) & 1;
                int oc = n0 + (nj * 2 + j2) * 8 + (lane & 7);
                int g = kg + half;
                unsigned off = oc * 128 + ((g ^ (oc & 7)) << 4);
                uint32_t t[4];
                ldmx4(t, BH + off);
                bH[nj*2][0] = t[0]; bH[nj*2][1] = t[1]; bH[nj*2+1][0] = t[2]; bH[nj*2+1][1] = t[3];
                ldmx4(t, BL + off);
                bL[nj*2][0] = t[0]; bL[nj*2][1] = t[1]; bL[nj*2+1][0] = t[2]; bL[nj*2+1][1] = t[3];
            }
            #pragma unroll
            for (int ms = 0; ms < 2; ms++)
                #pragma unroll
                for (int ns = 0; ns < 8; ns++) {
                    mma16816(acc[ms][ns], aH[ms], bH[ns]);
                    mma16816(acc[ms][ns], aH[ms], bL[ns]);
                    mma16816(acc[ms][ns], aL[ms], bH[ns]);
                }
        }
    };

    float v[32];
    loadB(0, 0); cp_commit();
    fetchA(0, v); storeA(0, v);
    cp_wait0();
    __syncthreads();

    int nk = K >> 6;
    for (int kt = 0; kt < nk; kt++) {
        int st = kt & 1;
        bool more = (kt + 1) < nk;
        if (more) {
            loadB(st ^ 1, (kt + 1) << 6); cp_commit();
            fetchA((kt + 1) << 6, v);
        }
        compute(st);
        if (more) {
            storeA(st ^ 1, v);
            cp_wait0();
        }
        __syncthreads();
    }

    float* T = (float*)sm;   // [128][132]
    if (!tokmaj) {
        #pragma unroll
        for (int ms = 0; ms < 2; ms++)
            #pragma unroll
            for (int ns = 0; ns < 8; ns++)
                #pragma unroll
                for (int e = 0; e < 4; e++) {
                    int pix = m0 + ms * 16 + (lane >> 2) + (e >> 1) * 8;
                    int oc  = n0 + ns * 8 + (lane & 3) * 2 + (e & 1);
                    T[oc * 132 + pix] = acc[ms][ns][e];
                }
        __syncthreads();
        #pragma unroll
        for (int it = 0; it < 16; it++) {
            int f = it * 256 + tid;
            int oc = f >> 5, p4 = (f & 31) * 4;
            float4 vv = *(float4*)&T[oc * 132 + p4];
            size_t go = ((size_t)bimg * Cout + ocbase + oc) * 1024 + pixbase + p4;
            if (addp) {
                float4 a = *(const float4*)(addp + go);
                vv.x += a.x; vv.y += a.y; vv.z += a.z; vv.w += a.w;
            }
            *(float4*)(outp + go) = vv;
        }
    } else {
        #pragma unroll
        for (int ms = 0; ms < 2; ms++)
            #pragma unroll
            for (int ns = 0; ns < 8; ns++)
                #pragma unroll
                for (int e = 0; e < 4; e++) {
                    int pix = m0 + ms * 16 + (lane >> 2) + (e >> 1) * 8;
                    int oc  = n0 + ns * 8 + (lane & 3) * 2 + (e & 1);
                    T[pix * 132 + oc] = acc[ms][ns][e];
                }
        __syncthreads();
        #pragma unroll
        for (int it = 0; it < 16; it++) {
            int f = it * 256 + tid;
            int pix = f >> 5, o4 = (f & 31) * 4;
            float4 vv = *(float4*)&T[pix * 132 + o4];
            size_t go = ((size_t)bimg * 1024 + pixbase + pix) * Cout + ocbase + o4;
            *(float4*)(outp + go) = vv;
        }
    }
}

// ---------------- weight prep ----------------
__global__ __launch_bounds__(256) void cvt_w(
    __nv_bfloat16* __restrict__ hi, __nv_bfloat16* __restrict__ lo,
    const float* __restrict__ s, int n)
{
    int i = blockIdx.x * 256 + threadIdx.x;
    if (i < n) {
        float v = s[i];
        __nv_bfloat16 h = __float2bfloat16(v);
        hi[i] = h;
        lo[i] = __float2bfloat16(v - __bfloat162float(h));
    }
}
__global__ __launch_bounds__(256) void cvt_conv_w(
    __nv_bfloat16* __restrict__ hi, __nv_bfloat16* __restrict__ lo,
    const float* __restrict__ s, int KK, int n)
{
    int i = blockIdx.x * 256 + threadIdx.x;
    if (i < n) {
        int oc = i / (KK * 256);
        int r = i - oc * KK * 256;
        int tap = r >> 8, ic = r & 255;
        float v = s[((size_t)(oc * 256 + ic)) * KK + tap];
        __nv_bfloat16 h = __float2bfloat16(v);
        hi[i] = h;
        lo[i] = __float2bfloat16(v - __bfloat162float(h));
    }
}

// ---------------- layernorm over channels (NCHW) ----------------
__global__ __launch_bounds__(256) void ln_kernel(
    const float* __restrict__ x, const float* __restrict__ w,
    const float* __restrict__ bias, float* __restrict__ y)
{
    int b = blockIdx.y;
    int n0 = blockIdx.x * 32;
    int nx = threadIdx.x & 31;
    int cg = threadIdx.x >> 5;
    const float* xb = x + (size_t)b * C * HW + n0 + nx;
    float v[32];
    float s = 0.f, ss = 0.f;
    #pragma unroll
    for (int i = 0; i < 32; i++) {
        float t = xb[(size_t)(cg * 32 + i) * HW];
        v[i] = t; s += t; ss += t * t;
    }
    __shared__ float rs[8][32], rss[8][32];
    rs[cg][nx] = s; rss[cg][nx] = ss;
    __syncthreads();
    float tot = 0.f, tot2 = 0.f;
    #pragma unroll
    for (int g = 0; g < 8; g++) { tot += rs[g][nx]; tot2 += rss[g][nx]; }
    float mu = tot * (1.f / 256.f);
    float var = tot2 * (1.f / 256.f) - mu * mu;
    float rstd = rsqrtf(var + 1e-5f);
    float* yb = y + (size_t)b * C * HW + n0 + nx;
    #pragma unroll
    for (int i = 0; i < 32; i++) {
        int c = cg * 32 + i;
        yb[(size_t)c * HW] = (v[i] - mu) * rstd * w[c] + bias[c];
    }
}

// =====================================================================
// tensor-core flash attention. d=64 per head, N=1024.
// Q,K token-major [b][1024][qs/ks] (head cols at hoff). V channel-major
// [b][256][1024]. O channel-major. grid (16 qtiles of 64, 4 heads, 8 b),
// 128 threads (4 warps, warp = 16 q rows). dyn smem 49152.
// layout: Qh 8K | Ql 8K | Kh 8K | Kl 8K | Vh 8K | Vl 8K  (row=128B, swizzled)
// =====================================================================
__global__ __launch_bounds__(128) void attn_mma(
    const float* __restrict__ Qp, const float* __restrict__ Kp,
    const float* __restrict__ Vp, float* __restrict__ O,
    int qs, int ks)
{
    extern __shared__ char sm[];
    uint32_t sbase = smem_u32(sm);
    const uint32_t QH = sbase, QL = sbase + 8192, KH = sbase + 16384, KL = sbase + 24576;
    const uint32_t VH = sbase + 32768, VL = sbase + 40960;

    int tid = threadIdx.x;
    int w = tid >> 5, lane = tid & 31;
    int q0 = blockIdx.x * 64;
    int hoff = blockIdx.y * 64;
    int bimg = blockIdx.z;
    int m0 = w * 16;

    // load Q once: rows q (64) x 64 d, scaled by 0.125, bf16 split
    {
        int q = tid >> 1, dseg = (tid & 1) * 32;
        const float* src = Qp + ((size_t)bimg * 1024 + q0 + q) * qs + hoff + dseg;
        #pragma unroll
        for (int i = 0; i < 4; i++) {
            float4 v0 = *(const float4*)(src + i * 8);
            float4 v1 = *(const float4*)(src + i * 8 + 4);
            unsigned h0, l0, h1, l1, h2v, l2v, h3, l3;
            splitpk(v0.x * 0.125f, v0.y * 0.125f, h0, l0);
            splitpk(v0.z * 0.125f, v0.w * 0.125f, h1, l1);
            splitpk(v1.x * 0.125f, v1.y * 0.125f, h2v, l2v);
            splitpk(v1.z * 0.125f, v1.w * 0.125f, h3, l3);
            int g = (dseg >> 3) + i;
            unsigned off = q * 128 + ((g ^ (q & 7)) << 4);
            *(uint4*)(sm + off) = make_uint4(h0, h1, h2v, h3);
            *(uint4*)(sm + 8192 + off) = make_uint4(l0, l1, l2v, l3);
        }
    }

    float oacc[8][4] = {};
    float mrun[2], lrun[2];
    mrun[0] = mrun[1] = -1e30f;
    lrun[0] = lrun[1] = 0.f;

    for (int c0 = 0; c0 < 1024; c0 += 64) {
        __syncthreads();
        // K chunk: rows kv x 64 d (token-major source)
        {
            int kv = tid >> 1, dseg = (tid & 1) * 32;
            const float* src = Kp + ((size_t)bimg * 1024 + c0 + kv) * ks + hoff + dseg;
            #pragma unroll
            for (int i = 0; i < 4; i++) {
                float4 v0 = *(const float4*)(src + i * 8);
                float4 v1 = *(const float4*)(src + i * 8 + 4);
                unsigned h0, l0, h1, l1, h2v, l2v, h3, l3;
                splitpk(v0.x, v0.y, h0, l0);
                splitpk(v0.z, v0.w, h1, l1);
                splitpk(v1.x, v1.y, h2v, l2v);
                splitpk(v1.z, v1.w, h3, l3);
                int g = (dseg >> 3) + i;
                unsigned off = kv * 128 + ((g ^ (kv & 7)) << 4);
                *(uint4*)(sm + 16384 + off) = make_uint4(h0, h1, h2v, h3);
                *(uint4*)(sm + 24576 + off) = make_uint4(l0, l1, l2v, l3);
            }
        }
        // V chunk: rows d (64) x 64 kv (channel-major source)
        {
            int d = tid >> 1, kseg = (tid & 1) * 32;
            const float* src = Vp + ((size_t)bimg * 256 + hoff + d) * 1024 + c0 + kseg;
            #pragma unroll
            for (int i = 0; i < 4; i++) {
                float4 v0 = *(const float4*)(src + i * 8);
                float4 v1 = *(const float4*)(src + i * 8 + 4);
                unsigned h0, l0, h1, l1, h2v, l2v, h3, l3;
                splitpk(v0.x, v0.y, h0, l0);
                splitpk(v0.z, v0.w, h1, l1);
                splitpk(v1.x, v1.y, h2v, l2v);
                splitpk(v1.z, v1.w, h3, l3);
                int g = (kseg >> 3) + i;
                unsigned off = d * 128 + ((g ^ (d & 7)) << 4);
                *(uint4*)(sm + 32768 + off) = make_uint4(h0, h1, h2v, h3);
                *(uint4*)(sm + 40960 + off) = make_uint4(l0, l1, l2v, l3);
            }
        }
        __syncthreads();

        // S = Q K^T  (warp: 16 q x 64 kv)
        float s[8][4] = {};
        #pragma unroll
        for (int ks4 = 0; ks4 < 4; ks4++) {
            int kg = ks4 * 2;
            uint32_t aH[4], aL[4];
            {
                int sel = lane >> 3;
                int row = m0 + (sel & 1) * 8 + (lane & 7);
                int g = kg + (sel >> 1);
                unsigned off = row * 128 + ((g ^ (row & 7)) << 4);
                ldmx4(aH, QH + off);
                ldmx4(aL, QL + off);
            }
            #pragma unroll
            for (int nj = 0; nj < 4; nj++) {
                int j2 = lane >> 4, half = (lane >> 3) & 1;
                int kv = (nj * 2 + j2) * 8 + (lane & 7);
                int g = kg + half;
                unsigned off = kv * 128 + ((g ^ (kv & 7)) << 4);
                uint32_t t[4], bh0[2], bh1[2], bl0[2], bl1[2];
                ldmx4(t, KH + off);
                bh0[0] = t[0]; bh0[1] = t[1]; bh1[0] = t[2]; bh1[1] = t[3];
                ldmx4(t, KL + off);
                bl0[0] = t[0]; bl0[1] = t[1]; bl1[0] = t[2]; bl1[1] = t[3];
                mma16816(s[nj*2], aH, bh0);   mma16816(s[nj*2+1], aH, bh1);
                mma16816(s[nj*2], aH, bl0);   mma16816(s[nj*2+1], aH, bl1);
                mma16816(s[nj*2], aL, bh0);   mma16816(s[nj*2+1], aL, bh1);
            }
        }

        // online softmax (rows g=lane>>2 and g+8)
        #pragma unroll
        for (int r = 0; r < 2; r++) {
            int e0 = r * 2;   // c-reg index base: 0,1 row g; 2,3 row g+8
            float mx = -1e30f;
            #pragma unroll
            for (int e = 0; e < 8; e++)
                mx = fmaxf(mx, fmaxf(s[e][e0], s[e][e0+1]));
            mx = fmaxf(mx, __shfl_xor_sync(0xffffffffu, mx, 1));
            mx = fmaxf(mx, __shfl_xor_sync(0xffffffffu, mx, 2));
            float mnew = fmaxf(mrun[r], mx);
            float corr = __expf(mrun[r] - mnew);
            float rsum = 0.f;
            #pragma unroll
            for (int e = 0; e < 8; e++) {
                float p0 = __expf(s[e][e0] - mnew);
                float p1 = __expf(s[e][e0+1] - mnew);
                s[e][e0] = p0; s[e][e0+1] = p1;
                rsum += p0 + p1;
            }
            rsum += __shfl_xor_sync(0xffffffffu, rsum, 1);
            rsum += __shfl_xor_sync(0xffffffffu, rsum, 2);
            lrun[r] = lrun[r] * corr + rsum;
            mrun[r] = mnew;
            #pragma unroll
            for (int e = 0; e < 8; e++) {
                oacc[e][e0] *= corr; oacc[e][e0+1] *= corr;
            }
        }

        // O += P V   (A = P from regs, B = V[d][kv])
        #pragma unroll
        for (int ks4 = 0; ks4 < 4; ks4++) {
            int e = ks4 * 2;
            uint32_t aPh[4], aPl[4];
            splitpk(s[e][0],   s[e][1],   aPh[0], aPl[0]);
            splitpk(s[e][2],   s[e][3],   aPh[1], aPl[1]);
            splitpk(s[e+1][0], s[e+1][1], aPh[2], aPl[2]);
            splitpk(s[e+1][2], s[e+1][3], aPh[3], aPl[3]);
            int kg = ks4 * 2;
            #pragma unroll
            for (int nj = 0; nj < 4; nj++) {
                int j2 = lane >> 4, half = (lane >> 3) & 1;
                int d = (nj * 2 + j2) * 8 + (lane & 7);
                int g = kg + half;
                unsigned off = d * 128 + ((g ^ (d & 7)) << 4);
                uint32_t t[4], bh0[2], bh1[2], bl0[2], bl1[2];
                ldmx4(t, VH + off);
                bh0[0] = t[0]; bh0[1] = t[1]; bh1[0] = t[2]; bh1[1] = t[3];
                ldmx4(t, VL + off);
                bl0[0] = t[0]; bl0[1] = t[1]; bl1[0] = t[2]; bl1[1] = t[3];
                mma16816(oacc[nj*2], aPh, bh0);   mma16816(oacc[nj*2+1], aPh, bh1);
                mma16816(oacc[nj*2], aPh, bl0);   mma16816(oacc[nj*2+1], aPh, bl1);
                mma16816(oacc[nj*2], aPl, bh0);   mma16816(oacc[nj*2+1], aPl, bh1);
            }
        }
    }

    // epilogue: normalize, transpose via smem, store channel-major
    __syncthreads();
    float* Os = (float*)sm;   // [64 d][68]
    float li0 = 1.f / lrun[0], li1 = 1.f / lrun[1];
    #pragma unroll
    for (int nt = 0; nt < 8; nt++)
        #pragma unroll
        for (int e = 0; e < 4; e++) {
            int d = nt * 8 + (lane & 3) * 2 + (e & 1);
            int q = m0 + (lane >> 2) + (e >> 1) * 8;
            Os[d * 68 + q] = oacc[nt][e] * ((e & 2) ? li1 : li0);
        }
    __syncthreads();
    {
        int d = tid >> 1, qseg = (tid & 1) * 32;
        float* dst = O + ((size_t)bimg * 256 + hoff + d) * 1024 + q0 + qseg;
        #pragma unroll
        for (int i = 0; i < 8; i++)
            *(float4*)(dst + i * 4) = *(float4*)&Os[d * 68 + qseg + i * 4];
    }
}

// ---------------- depthwise 3x3 + exact GELU ----------------
__global__ __launch_bounds__(256) void dwconv_gelu(
    const float* __restrict__ X, const float* __restrict__ W, float* __restrict__ Y)
{
    int idx = blockIdx.x * 256 + threadIdx.x;
    int x = idx & 31;
    int y = (idx >> 5) & 31;
    int c = (idx >> 10) & 1023;
    int b = idx >> 20;
    const float* xb = X + ((size_t)b * HIDDEN + c) * HW;
    const float* wc = W + c * 9;
    float acc = 0.f;
    #pragma unroll
    for (int dy = 0; dy < 3; dy++) {
        int iy = y + dy - 1;
        #pragma unroll
        for (int dx = 0; dx < 3; dx++) {
            int ix = x + dx - 1;
            if ((unsigned)iy < 32u && (unsigned)ix < 32u)
                acc += wc[dy * 3 + dx] * xb[(iy << 5) + ix];
        }
    }
    Y[idx] = 0.5f * acc * (1.f + erff(acc * 0.70710678118654752440f));
}

// ---------------- host ----------------
extern "C" void kernel_launch(void* const* d_in, const int* in_sizes, int n_in,
                              void* d_out, int out_size)
{
    const float* aop      = (const float*)d_in[0];
    const float* dop      = (const float*)d_in[1];
    const float* w_qconv  = (const float*)d_in[2];
    const float* w_kvconv = (const float*)d_in[3];
    const float* lnq1_w   = (const float*)d_in[4];
    const float* lnq1_b   = (const float*)d_in[5];
    const float* lnkv1_w  = (const float*)d_in[6];
    const float* lnkv1_b  = (const float*)d_in[7];
    const float* lnq2_w   = (const float*)d_in[8];
    const float* lnq2_b   = (const float*)d_in[9];
    const float* lnkv2_w  = (const float*)d_in[10];
    const float* lnkv2_b  = (const float*)d_in[11];
    const float* lnffn_w  = (const float*)d_in[12];
    const float* lnffn_b  = (const float*)d_in[13];
    const float* saq_qkv  = (const float*)d_in[14];
    const float* saq_proj = (const float*)d_in[15];
    const float* sakv_qkv = (const float*)d_in[16];
    const float* sakv_proj= (const float*)d_in[17];
    const float* ca_q     = (const float*)d_in[18];
    const float* ca_k     = (const float*)d_in[19];
    const float* ca_v     = (const float*)d_in[20];
    const float* ca_proj  = (const float*)d_in[21];
    const float* leff_in  = (const float*)d_in[22];
    const float* leff_dw  = (const float*)d_in[23];
    const float* leff_out = (const float*)d_in[24];
    float* out = (float*)d_out;

    float *qbr, *kvbr, *tmp, *qb, *kb, *vb, *att, *h1, *h2;
    __nv_bfloat16* wbf;
    cudaGetSymbolAddress((void**)&qbr,  g_qbranch);
    cudaGetSymbolAddress((void**)&kvbr, g_kvbranch);
    cudaGetSymbolAddress((void**)&tmp,  g_tmp);
    cudaGetSymbolAddress((void**)&qb,   g_qb);
    cudaGetSymbolAddress((void**)&kb,   g_kb);
    cudaGetSymbolAddress((void**)&vb,   g_vb);
    cudaGetSymbolAddress((void**)&att,  g_attn);
    cudaGetSymbolAddress((void**)&h1,   g_h1);
    cudaGetSymbolAddress((void**)&h2,   g_h2);
    cudaGetSymbolAddress((void**)&wbf,  g_wbf);

    const int MM_SMEM = 131072;
    const int ATT_SMEM = 49152;
    cudaFuncSetAttribute(attn_mma, cudaFuncAttributeMaxDynamicSharedMemorySize, ATT_SMEM);
    cudaFuncSetAttribute(mm_tc<0,0>, cudaFuncAttributeMaxDynamicSharedMemorySize, MM_SMEM);
    cudaFuncSetAttribute(mm_tc<3,1>, cudaFuncAttributeMaxDynamicSharedMemorySize, MM_SMEM);
    cudaFuncSetAttribute(mm_tc<5,2>, cudaFuncAttributeMaxDynamicSharedMemorySize, MM_SMEM);

    // weight prep
    cvt_conv_w<<<(int)((SZ3+255)/256), 256>>>(wbf+OC3, wbf+OC3+SZ3, w_qconv, 9, (int)SZ3);
    cvt_conv_w<<<(int)((SZ5+255)/256), 256>>>(wbf+OC5, wbf+OC5+SZ5, w_kvconv, 25, (int)SZ5);
    cvt_w<<<(int)((SZQKV+255)/256), 256>>>(wbf+OSAQ,  wbf+OSAQ+SZQKV,  saq_qkv,  (int)SZQKV);
    cvt_w<<<(int)((SZQKV+255)/256), 256>>>(wbf+OSAKV, wbf+OSAKV+SZQKV, sakv_qkv, (int)SZQKV);
    cvt_w<<<(int)((SZCC+255)/256), 256>>>(wbf+OSAQP,  wbf+OSAQP+SZCC,  saq_proj, (int)SZCC);
    cvt_w<<<(int)((SZCC+255)/256), 256>>>(wbf+OSAKVP, wbf+OSAKVP+SZCC, sakv_proj,(int)SZCC);
    cvt_w<<<(int)((SZCC+255)/256), 256>>>(wbf+OCAQ, wbf+OCAQ+SZCC, ca_q, (int)SZCC);
    cvt_w<<<(int)((SZCC+255)/256), 256>>>(wbf+OCAK, wbf+OCAK+SZCC, ca_k, (int)SZCC);
    cvt_w<<<(int)((SZCC+255)/256), 256>>>(wbf+OCAV, wbf+OCAV+SZCC, ca_v, (int)SZCC);
    cvt_w<<<(int)((SZCC+255)/256), 256>>>(wbf+OCAP, wbf+OCAP+SZCC, ca_proj, (int)SZCC);
    cvt_w<<<(int)((SZLF+255)/256), 256>>>(wbf+OLIN,  wbf+OLIN+SZLF,  leff_in,  (int)SZLF);
    cvt_w<<<(int)((SZLF+255)/256), 256>>>(wbf+OLOUT, wbf+OLOUT+SZLF, leff_out, (int)SZLF);

    dim3 gC(8, 2, NB), gQK(8, 4, NB), gV(8, 2, NB), gHID(8, 8, NB);
    dim3 gLN(32, NB), gATT(16, 4, NB);
    const __nv_bfloat16* wsaq = wbf + OSAQ;
    const __nv_bfloat16* wsakv = wbf + OSAKV;

    // ---- q branch ----
    mm_tc<3,1><<<gC, 256, MM_SMEM>>>(wbf+OC3, wbf+OC3+SZ3, aop, qbr, nullptr, 2304, 256, 256, 0);
    ln_kernel<<<gLN, 256>>>(qbr, lnq1_w, lnq1_b, tmp);
    mm_tc<0,0><<<gQK, 256, MM_SMEM>>>(wsaq, wsaq + SZQKV, tmp, h2, nullptr, 256, 256, 512, 1);
    mm_tc<0,0><<<gV, 256, MM_SMEM>>>(wsaq + 512*256, wsaq + SZQKV + 512*256, tmp, vb, nullptr, 256, 256, 256, 0);
    attn_mma<<<gATT, 128, ATT_SMEM>>>(h2, h2 + 256, vb, att, 512, 512);
    mm_tc<0,0><<<gC, 256, MM_SMEM>>>(wbf+OSAQP, wbf+OSAQP+SZCC, att, qbr, qbr, 256, 256, 256, 0);

    // ---- kv branch ----
    mm_tc<5,2><<<gC, 256, MM_SMEM>>>(wbf+OC5, wbf+OC5+SZ5, dop, kvbr, nullptr, 6400, 256, 256, 0);
    ln_kernel<<<gLN, 256>>>(kvbr, lnkv1_w, lnkv1_b, tmp);
    mm_tc<0,0><<<gQK, 256, MM_SMEM>>>(wsakv, wsakv + SZQKV, tmp, h2, nullptr, 256, 256, 512, 1);
    mm_tc<0,0><<<gV, 256, MM_SMEM>>>(wsakv + 512*256, wsakv + SZQKV + 512*256, tmp, vb, nullptr, 256, 256, 256, 0);
    attn_mma<<<gATT, 128, ATT_SMEM>>>(h2, h2 + 256, vb, att, 512, 512);
    mm_tc<0,0><<<gC, 256, MM_SMEM>>>(wbf+OSAKVP, wbf+OSAKVP+SZCC, att, kvbr, kvbr, 256, 256, 256, 0);

    // ---- cross attention ----
    ln_kernel<<<gLN, 256>>>(qbr, lnq2_w, lnq2_b, tmp);
    mm_tc<0,0><<<gV, 256, MM_SMEM>>>(wbf+OCAQ, wbf+OCAQ+SZCC, tmp, qb, nullptr, 256, 256, 256, 1);
    ln_kernel<<<gLN, 256>>>(kvbr, lnkv2_w, lnkv2_b, tmp);
    mm_tc<0,0><<<gV, 256, MM_SMEM>>>(wbf+OCAK, wbf+OCAK+SZCC, tmp, kb, nullptr, 256, 256, 256, 1);
    mm_tc<0,0><<<gV, 256, MM_SMEM>>>(wbf+OCAV, wbf+OCAV+SZCC, tmp, vb, nullptr, 256, 256, 256, 0);
    attn_mma<<<gATT, 128, ATT_SMEM>>>(qb, kb, vb, att, 256, 256);
    mm_tc<0,0><<<gC, 256, MM_SMEM>>>(wbf+OCAP, wbf+OCAP+SZCC, att, out, qbr, 256, 256, 256, 0);

    // ---- LeFF ----
    ln_kernel<<<gLN, 256>>>(out, lnffn_w, lnffn_b, tmp);
    mm_tc<0,0><<<gHID, 256, MM_SMEM>>>(wbf+OLIN, wbf+OLIN+SZLF, tmp, h1, nullptr, 256, 256, 1024, 0);
    dwconv_gelu<<<(NB * HIDDEN * HW) / 256, 256>>>(h1, leff_dw, h2);
    mm_tc<0,0><<<gC, 256, MM_SMEM>>>(wbf+OLOUT, wbf+OLOUT+SZLF, h2, out, out, 1024, 1024, 256, 0);
}

// round 9
// speedup vs baseline: 2.4707x; 1.2092x over previous
#include <cuda_runtime.h>
#include <cuda_bf16.h>
#include <math.h>
#include <stdint.h>

#define NB 8
#define C 256
#define HW 1024
#define HIDDEN 1024

__device__ float g_qbranch[NB*C*HW];
__device__ float g_kvbranch[NB*C*HW];
__device__ float g_h1[NB*HIDDEN*HW];
__device__ float g_h2[NB*HIDDEN*HW];
__device__ __align__(256) __nv_bfloat16 g_wbf[7100000];
__device__ __align__(256) __nv_bfloat16 g_bln[4194304];   // 2 planes x (8,1024,256)
__device__ __align__(256) __nv_bfloat16 g_bqk[8388608];   // 2 planes x (8,1024,512) or cross-attn q/k
__device__ __align__(256) __nv_bfloat16 g_bv[4194304];    // 2 planes x (8,256,1024)
__device__ __align__(256) __nv_bfloat16 g_batt[4194304];  // 2 planes x (8,1024,256)

#define OC3    0ull
#define SZ3    589824ull
#define OC5    1179648ull
#define SZ5    1638400ull
#define OSAQ   4456448ull
#define SZQKV  196608ull
#define OSAKV  4849664ull
#define OSAQP  5242880ull
#define SZCC   65536ull
#define OSAKVP 5373952ull
#define OCAQ   5505024ull
#define OCAK   5636096ull
#define OCAV   5767168ull
#define OCAP   5898240ull
#define OLIN   6029312ull
#define SZLF   262144ull
#define OLOUT  6553600ull

// ---------------- helpers ----------------
__device__ __forceinline__ uint32_t smem_u32(const void* p) {
    uint32_t a;
    asm("{ .reg .u64 t; cvta.to.shared.u64 t, %1; cvt.u32.u64 %0, t; }" : "=r"(a) : "l"(p));
    return a;
}
__device__ __forceinline__ void cp16(void* dst, const void* src) {
    unsigned d = (unsigned)__cvta_generic_to_shared(dst);
    asm volatile("cp.async.ca.shared.global [%0], [%1], 16;" :: "r"(d), "l"(src));
}
__device__ __forceinline__ void cp_commit() { asm volatile("cp.async.commit_group;" ::: "memory"); }
__device__ __forceinline__ void cp_wait0()  { asm volatile("cp.async.wait_group 0;" ::: "memory"); }

__device__ __forceinline__ void ldmx4(uint32_t* r, uint32_t addr) {
    asm volatile("ldmatrix.sync.aligned.m8n8.x4.shared.b16 {%0,%1,%2,%3}, [%4];"
        : "=r"(r[0]), "=r"(r[1]), "=r"(r[2]), "=r"(r[3]) : "r"(addr));
}
__device__ __forceinline__ void mma16816(float* c, const uint32_t* a, const uint32_t* b) {
    asm volatile("mma.sync.aligned.m16n8k16.row.col.f32.bf16.bf16.f32 "
        "{%0,%1,%2,%3}, {%4,%5,%6,%7}, {%8,%9}, {%0,%1,%2,%3};"
        : "+f"(c[0]), "+f"(c[1]), "+f"(c[2]), "+f"(c[3])
        : "r"(a[0]), "r"(a[1]), "r"(a[2]), "r"(a[3]), "r"(b[0]), "r"(b[1]));
}
__device__ __forceinline__ unsigned pkbf(float a, float b) {
    __nv_bfloat16 ha = __float2bfloat16(a), hb = __float2bfloat16(b);
    return ((unsigned)__bfloat16_as_ushort(hb) << 16) | __bfloat16_as_ushort(ha);
}
__device__ __forceinline__ void splitpk(float a, float b, unsigned& hi, unsigned& lo) {
    __nv_bfloat16 ha = __float2bfloat16(a), hb = __float2bfloat16(b);
    hi = ((unsigned)__bfloat16_as_ushort(hb) << 16) | __bfloat16_as_ushort(ha);
    lo = pkbf(a - __bfloat162float(ha), b - __bfloat162float(hb));
}

// =====================================================================
// mma.sync GEMM / implicit conv.
// ABF=0: act fp32 channel-major [b][SA][1024] (KW taps for conv)
// ABF=1: pre-split bf16 A, token-major rows of arow elems (ahi/alo planes)
// outmode 0: fp32 chanmaj (+addp); 1: bf16 tokmaj planes; 2: bf16 chanmaj planes
// grid (8 pixtiles, Cout/128, NB), 256 threads, dyn smem 131072
// =====================================================================
template<int KW, int PAD, int ABF>
__global__ __launch_bounds__(256, 1) void mm_tc(
    const __nv_bfloat16* __restrict__ whi, const __nv_bfloat16* __restrict__ wlo,
    const float* __restrict__ act,
    const __nv_bfloat16* __restrict__ ahi, const __nv_bfloat16* __restrict__ alo, int arow,
    float* __restrict__ outp, const float* __restrict__ addp,
    __nv_bfloat16* __restrict__ obhi, __nv_bfloat16* __restrict__ oblo,
    int K, int SA, int Cout, int outmode)
{
    extern __shared__ char sm[];
    int tid = threadIdx.x;
    int pixbase = blockIdx.x * 128;
    int ocbase = blockIdx.y * 128;
    int bimg = blockIdx.z;
    int w = tid >> 5, lane = tid & 31;
    int m0 = (w >> 1) * 32;
    int n0 = (w & 1) * 64;
    uint32_t sbase = smem_u32(sm);

    float acc[2][8][4] = {};
    int apix = tid & 127, ahalf = tid >> 7;

    auto fetchA = [&](int kk, float* v) {
        if (KW == 0) {
            const float* p = act + ((size_t)bimg * SA + kk + ahalf * 32) * 1024 + pixbase + apix;
            #pragma unroll
            for (int i = 0; i < 32; i++) v[i] = p[(size_t)i * 1024];
        } else {
            int kbase = kk + ahalf * 32;
            int tap = kbase >> 8, ic0 = kbase & 255;
            int dy = tap / KW - PAD, dx = tap % KW - PAD;
            int p = pixbase + apix;
            int iy = (p >> 5) + dy, ix = (p & 31) + dx;
            bool ok = ((unsigned)iy < 32u) && ((unsigned)ix < 32u);
            const float* src = act + ((size_t)bimg * 256 + ic0) * 1024 + (iy << 5) + ix;
            #pragma unroll
            for (int i = 0; i < 32; i++) v[i] = ok ? src[(size_t)i * 1024] : 0.f;
        }
    };
    auto storeA = [&](int st, const float* v) {
        char* AH = sm + st * 65536;
        char* AL = AH + 16384;
        #pragma unroll
        for (int gi = 0; gi < 4; gi++) {
            int g = ahalf * 4 + gi;
            unsigned hh[4], ll[4];
            #pragma unroll
            for (int m = 0; m < 4; m++)
                splitpk(v[gi * 8 + 2 * m], v[gi * 8 + 2 * m + 1], hh[m], ll[m]);
            unsigned off = apix * 128 + ((g ^ (apix & 7)) << 4);
            *(uint4*)(AH + off) = make_uint4(hh[0], hh[1], hh[2], hh[3]);
            *(uint4*)(AL + off) = make_uint4(ll[0], ll[1], ll[2], ll[3]);
        }
    };
    auto loadAbf = [&](int st, int kk) {
        char* base = sm + st * 65536;
        #pragma unroll
        for (int i = 0; i < 8; i++) {
            int idx = tid + i * 256;
            int plane = idx >> 10, r = idx & 1023;
            int pix = r >> 3, g = r & 7;
            const __nv_bfloat16* src = (plane ? alo : ahi)
                + ((size_t)bimg * 1024 + pixbase + pix) * arow + kk + g * 8;
            unsigned off = pix * 128 + ((g ^ (pix & 7)) << 4);
            cp16(base + plane * 16384 + off, src);
        }
    };
    auto loadB = [&](int st, int kk) {
        char* base = sm + st * 65536 + 32768;
        #pragma unroll
        for (int i = 0; i < 8; i++) {
            int idx = tid + i * 256;
            int plane = idx >> 10, r = idx & 1023;
            int oc = r >> 3, g = r & 7;
            const __nv_bfloat16* src = (plane ? wlo : whi) + (size_t)(ocbase + oc) * K + kk + g * 8;
            unsigned off = oc * 128 + ((g ^ (oc & 7)) << 4);
            cp16(base + plane * 16384 + off, src);
        }
    };
    auto compute = [&](int st) {
        uint32_t AH = sbase + st * 65536, AL = AH + 16384;
        uint32_t BH = AH + 32768, BL = AH + 49152;
        #pragma unroll
        for (int ks = 0; ks < 4; ks++) {
            int kg = ks * 2;
            uint32_t aH[2][4], aL[2][4], bH[8][2], bL[8][2];
            #pragma unroll
            for (int ms = 0; ms < 2; ms++) {
                int sel = lane >> 3;
                int row = m0 + ms * 16 + (sel & 1) * 8 + (lane & 7);
                int g = kg + (sel >> 1);
                unsigned off = row * 128 + ((g ^ (row & 7)) << 4);
                ldmx4(aH[ms], AH + off);
                ldmx4(aL[ms], AL + off);
            }
            #pragma unroll
            for (int nj = 0; nj < 4; nj++) {
                int j2 = lane >> 4, half = (lane >> 3) & 1;
                int oc = n0 + (nj * 2 + j2) * 8 + (lane & 7);
                int g = kg + half;
                unsigned off = oc * 128 + ((g ^ (oc & 7)) << 4);
                uint32_t t[4];
                ldmx4(t, BH + off);
                bH[nj*2][0] = t[0]; bH[nj*2][1] = t[1]; bH[nj*2+1][0] = t[2]; bH[nj*2+1][1] = t[3];
                ldmx4(t, BL + off);
                bL[nj*2][0] = t[0]; bL[nj*2][1] = t[1]; bL[nj*2+1][0] = t[2]; bL[nj*2+1][1] = t[3];
            }
            #pragma unroll
            for (int ms = 0; ms < 2; ms++)
                #pragma unroll
                for (int ns = 0; ns < 8; ns++) {
                    mma16816(acc[ms][ns], aH[ms], bH[ns]);
                    mma16816(acc[ms][ns], aH[ms], bL[ns]);
                    mma16816(acc[ms][ns], aL[ms], bH[ns]);
                }
        }
    };

    int nk = K >> 6;
    if (ABF) {
        loadB(0, 0); loadAbf(0, 0);
        cp_commit();
        cp_wait0();
        __syncthreads();
        for (int kt = 0; kt < nk; kt++) {
            int st = kt & 1;
            bool more = (kt + 1) < nk;
            if (more) {
                loadB(st ^ 1, (kt + 1) << 6);
                loadAbf(st ^ 1, (kt + 1) << 6);
                cp_commit();
            }
            compute(st);
            if (more) cp_wait0();
            __syncthreads();
        }
    } else {
        float v[32];
        loadB(0, 0); cp_commit();
        fetchA(0, v); storeA(0, v);
        cp_wait0();
        __syncthreads();
        for (int kt = 0; kt < nk; kt++) {
            int st = kt & 1;
            bool more = (kt + 1) < nk;
            if (more) {
                loadB(st ^ 1, (kt + 1) << 6); cp_commit();
                fetchA((kt + 1) << 6, v);
            }
            compute(st);
            if (more) {
                storeA(st ^ 1, v);
                cp_wait0();
            }
            __syncthreads();
        }
    }

    float* T = (float*)sm;   // [128][132]
    if (outmode == 1) {
        #pragma unroll
        for (int ms = 0; ms < 2; ms++)
            #pragma unroll
            for (int ns = 0; ns < 8; ns++)
                #pragma unroll
                for (int e = 0; e < 4; e++) {
                    int pix = m0 + ms * 16 + (lane >> 2) + (e >> 1) * 8;
                    int oc  = n0 + ns * 8 + (lane & 3) * 2 + (e & 1);
                    T[pix * 132 + oc] = acc[ms][ns][e];
                }
        __syncthreads();
        #pragma unroll
        for (int it = 0; it < 16; it++) {
            int f = it * 256 + tid;
            int pix = f >> 5, o4 = (f & 31) * 4;
            float4 vv = *(float4*)&T[pix * 132 + o4];
            unsigned h0, l0, h1, l1;
            splitpk(vv.x, vv.y, h0, l0);
            splitpk(vv.z, vv.w, h1, l1);
            size_t idx = ((size_t)bimg * 1024 + pixbase + pix) * Cout + ocbase + o4;
            *(uint2*)(obhi + idx) = make_uint2(h0, h1);
            *(uint2*)(oblo + idx) = make_uint2(l0, l1);
        }
    } else {
        #pragma unroll
        for (int ms = 0; ms < 2; ms++)
            #pragma unroll
            for (int ns = 0; ns < 8; ns++)
                #pragma unroll
                for (int e = 0; e < 4; e++) {
                    int pix = m0 + ms * 16 + (lane >> 2) + (e >> 1) * 8;
                    int oc  = n0 + ns * 8 + (lane & 3) * 2 + (e & 1);
                    T[oc * 132 + pix] = acc[ms][ns][e];
                }
        __syncthreads();
        #pragma unroll
        for (int it = 0; it < 16; it++) {
            int f = it * 256 + tid;
            int oc = f >> 5, p4 = (f & 31) * 4;
            float4 vv = *(float4*)&T[oc * 132 + p4];
            if (outmode == 0) {
                size_t go = ((size_t)bimg * Cout + ocbase + oc) * 1024 + pixbase + p4;
                if (addp) {
                    float4 a = *(const float4*)(addp + go);
                    vv.x += a.x; vv.y += a.y; vv.z += a.z; vv.w += a.w;
                }
                *(float4*)(outp + go) = vv;
            } else {
                unsigned h0, l0, h1, l1;
                splitpk(vv.x, vv.y, h0, l0);
                splitpk(vv.z, vv.w, h1, l1);
                size_t idx = ((size_t)bimg * Cout + ocbase + oc) * 1024 + pixbase + p4;
                *(uint2*)(obhi + idx) = make_uint2(h0, h1);
                *(uint2*)(oblo + idx) = make_uint2(l0, l1);
            }
        }
    }
}

// ---------------- weight prep ----------------
__global__ __launch_bounds__(256) void cvt_w(
    __nv_bfloat16* __restrict__ hi, __nv_bfloat16* __restrict__ lo,
    const float* __restrict__ s, int n)
{
    int i = blockIdx.x * 256 + threadIdx.x;
    if (i < n) {
        float v = s[i];
        __nv_bfloat16 h = __float2bfloat16(v);
        hi[i] = h;
        lo[i] = __float2bfloat16(v - __bfloat162float(h));
    }
}
__global__ __launch_bounds__(256) void cvt_conv_w(
    __nv_bfloat16* __restrict__ hi, __nv_bfloat16* __restrict__ lo,
    const float* __restrict__ s, int KK, int n)
{
    int i = blockIdx.x * 256 + threadIdx.x;
    if (i < n) {
        int oc = i / (KK * 256);
        int r = i - oc * KK * 256;
        int tap = r >> 8, ic = r & 255;
        float v = s[((size_t)(oc * 256 + ic)) * KK + tap];
        __nv_bfloat16 h = __float2bfloat16(v);
        hi[i] = h;
        lo[i] = __float2bfloat16(v - __bfloat162float(h));
    }
}

// ---------------- layernorm: chanmaj fp32 in -> token-major bf16 hi/lo planes ----------------
__global__ __launch_bounds__(256) void ln_kernel(
    const float* __restrict__ x, const float* __restrict__ w,
    const float* __restrict__ bias,
    __nv_bfloat16* __restrict__ bhi, __nv_bfloat16* __restrict__ blo)
{
    int b = blockIdx.y;
    int n0 = blockIdx.x * 32;
    int nx = threadIdx.x & 31;
    int cg = threadIdx.x >> 5;
    const float* xb = x + (size_t)b * C * HW + n0 + nx;
    float v[32];
    float s = 0.f, ss = 0.f;
    #pragma unroll
    for (int i = 0; i < 32; i++) {
        float t = xb[(size_t)(cg * 32 + i) * HW];
        v[i] = t; s += t; ss += t * t;
    }
    __shared__ float rs[8][32], rss[8][32];
    rs[cg][nx] = s; rss[cg][nx] = ss;
    __syncthreads();
    float tot = 0.f, tot2 = 0.f;
    #pragma unroll
    for (int g = 0; g < 8; g++) { tot += rs[g][nx]; tot2 += rss[g][nx]; }
    float mu = tot * (1.f / 256.f);
    float var = tot2 * (1.f / 256.f) - mu * mu;
    float rstd = rsqrtf(var + 1e-5f);
    size_t orow = ((size_t)b * 1024 + n0 + nx) * 256 + cg * 32;
    #pragma unroll
    for (int i4 = 0; i4 < 4; i4++) {
        unsigned hh[4], ll[4];
        #pragma unroll
        for (int j = 0; j < 4; j++) {
            int i = i4 * 8 + j * 2;
            int c = cg * 32 + i;
            float a = (v[i]   - mu) * rstd * w[c]   + bias[c];
            float d = (v[i+1] - mu) * rstd * w[c+1] + bias[c+1];
            splitpk(a, d, hh[j], ll[j]);
        }
        *(uint4*)(bhi + orow + i4 * 8) = make_uint4(hh[0], hh[1], hh[2], hh[3]);
        *(uint4*)(blo + orow + i4 * 8) = make_uint4(ll[0], ll[1], ll[2], ll[3]);
    }
}

// =====================================================================
// tensor-core flash attention, pre-split bf16 inputs.
// Q,K token-major planes (rows qrow/krow elems, head at col hoff);
// V channel-major planes [b][256][1024]. Out token-major bf16 planes.
// grid (16 qtiles, 4 heads, 8 b), 128 threads. dyn smem 81920:
// Q 2x8K at 0 | stage0 K/V 32K at 16384 | stage1 at 49152
// =====================================================================
__global__ __launch_bounds__(128) void attn_mma(
    const __nv_bfloat16* __restrict__ qhi, const __nv_bfloat16* __restrict__ qlo, int qrow,
    const __nv_bfloat16* __restrict__ khi, const __nv_bfloat16* __restrict__ klo, int krow,
    const __nv_bfloat16* __restrict__ vhi, const __nv_bfloat16* __restrict__ vlo,
    __nv_bfloat16* __restrict__ ohi, __nv_bfloat16* __restrict__ olo)
{
    extern __shared__ char sm[];
    uint32_t sbase = smem_u32(sm);
    int tid = threadIdx.x;
    int w = tid >> 5, lane = tid & 31;
    int q0 = blockIdx.x * 64;
    int hoff = blockIdx.y * 64;
    int bimg = blockIdx.z;
    int m0 = w * 16;

    auto loadQ = [&]() {
        #pragma unroll
        for (int i = 0; i < 8; i++) {
            int idx = tid + i * 128;
            int plane = idx >> 9, r = idx & 511;
            int q = r >> 3, g = r & 7;
            const __nv_bfloat16* src = (plane ? qlo : qhi)
                + ((size_t)bimg * 1024 + q0 + q) * qrow + hoff + g * 8;
            unsigned off = q * 128 + ((g ^ (q & 7)) << 4);
            cp16(sm + plane * 8192 + off, src);
        }
    };
    auto loadKV = [&](int st, int c0) {
        char* base = sm + 16384 + st * 32768;
        #pragma unroll
        for (int i = 0; i < 16; i++) {
            int idx = tid + i * 128;
            int which = idx >> 10;          // 0=K 1=V
            int plane = (idx >> 9) & 1;
            int r = idx & 511;
            int row = r >> 3, g = r & 7;
            const __nv_bfloat16* src;
            if (which == 0)
                src = (plane ? klo : khi) + ((size_t)bimg * 1024 + c0 + row) * krow + hoff + g * 8;
            else
                src = (plane ? vlo : vhi) + ((size_t)bimg * 256 + hoff + row) * 1024 + c0 + g * 8;
            unsigned off = row * 128 + ((g ^ (row & 7)) << 4);
            cp16(base + which * 16384 + plane * 8192 + off, src);
        }
    };

    loadQ();
    loadKV(0, 0);
    cp_commit();

    float oacc[8][4] = {};
    float mrun[2], lrun[2];
    mrun[0] = mrun[1] = -1e30f;
    lrun[0] = lrun[1] = 0.f;

    cp_wait0();
    __syncthreads();

    const uint32_t QH = sbase, QL = sbase + 8192;
    for (int c = 0; c < 16; c++) {
        int st = c & 1;
        bool more = (c + 1) < 16;
        if (more) { loadKV(st ^ 1, (c + 1) * 64); cp_commit(); }

        uint32_t KB = sbase + 16384 + st * 32768;
        uint32_t KH = KB, KL = KB + 8192, VH = KB + 16384, VL = KB + 24576;

        // S = Q K^T
        float s[8][4] = {};
        #pragma unroll
        for (int ks4 = 0; ks4 < 4; ks4++) {
            int kg = ks4 * 2;
            uint32_t aH[4], aL[4];
            {
                int sel = lane >> 3;
                int row = m0 + (sel & 1) * 8 + (lane & 7);
                int g = kg + (sel >> 1);
                unsigned off = row * 128 + ((g ^ (row & 7)) << 4);
                ldmx4(aH, QH + off);
                ldmx4(aL, QL + off);
            }
            #pragma unroll
            for (int nj = 0; nj < 4; nj++) {
                int j2 = lane >> 4, half = (lane >> 3) & 1;
                int kv = (nj * 2 + j2) * 8 + (lane & 7);
                int g = kg + half;
                unsigned off = kv * 128 + ((g ^ (kv & 7)) << 4);
                uint32_t t[4], bh0[2], bh1[2], bl0[2], bl1[2];
                ldmx4(t, KH + off);
                bh0[0] = t[0]; bh0[1] = t[1]; bh1[0] = t[2]; bh1[1] = t[3];
                ldmx4(t, KL + off);
                bl0[0] = t[0]; bl0[1] = t[1]; bl1[0] = t[2]; bl1[1] = t[3];
                mma16816(s[nj*2], aH, bh0);   mma16816(s[nj*2+1], aH, bh1);
                mma16816(s[nj*2], aH, bl0);   mma16816(s[nj*2+1], aH, bl1);
                mma16816(s[nj*2], aL, bh0);   mma16816(s[nj*2+1], aL, bh1);
            }
        }
        #pragma unroll
        for (int e = 0; e < 8; e++)
            #pragma unroll
            for (int j = 0; j < 4; j++) s[e][j] *= 0.125f;

        // online softmax
        #pragma unroll
        for (int r = 0; r < 2; r++) {
            int e0 = r * 2;
            float mx = -1e30f;
            #pragma unroll
            for (int e = 0; e < 8; e++)
                mx = fmaxf(mx, fmaxf(s[e][e0], s[e][e0+1]));
            mx = fmaxf(mx, __shfl_xor_sync(0xffffffffu, mx, 1));
            mx = fmaxf(mx, __shfl_xor_sync(0xffffffffu, mx, 2));
            float mnew = fmaxf(mrun[r], mx);
            float corr = __expf(mrun[r] - mnew);
            float rsum = 0.f;
            #pragma unroll
            for (int e = 0; e < 8; e++) {
                float p0 = __expf(s[e][e0] - mnew);
                float p1 = __expf(s[e][e0+1] - mnew);
                s[e][e0] = p0; s[e][e0+1] = p1;
                rsum += p0 + p1;
            }
            rsum += __shfl_xor_sync(0xffffffffu, rsum, 1);
            rsum += __shfl_xor_sync(0xffffffffu, rsum, 2);
            lrun[r] = lrun[r] * corr + rsum;
            mrun[r] = mnew;
            #pragma unroll
            for (int e = 0; e < 8; e++) {
                oacc[e][e0] *= corr; oacc[e][e0+1] *= corr;
            }
        }

        // O += P V
        #pragma unroll
        for (int ks4 = 0; ks4 < 4; ks4++) {
            int e = ks4 * 2;
            uint32_t aPh[4], aPl[4];
            splitpk(s[e][0],   s[e][1],   aPh[0], aPl[0]);
            splitpk(s[e][2],   s[e][3],   aPh[1], aPl[1]);
            splitpk(s[e+1][0], s[e+1][1], aPh[2], aPl[2]);
            splitpk(s[e+1][2], s[e+1][3], aPh[3], aPl[3]);
            int kg = ks4 * 2;
            #pragma unroll
            for (int nj = 0; nj < 4; nj++) {
                int j2 = lane >> 4, half = (lane >> 3) & 1;
                int d = (nj * 2 + j2) * 8 + (lane & 7);
                int g = kg + half;
                unsigned off = d * 128 + ((g ^ (d & 7)) << 4);
                uint32_t t[4], bh0[2], bh1[2], bl0[2], bl1[2];
                ldmx4(t, VH + off);
                bh0[0] = t[0]; bh0[1] = t[1]; bh1[0] = t[2]; bh1[1] = t[3];
                ldmx4(t, VL + off);
                bl0[0] = t[0]; bl0[1] = t[1]; bl1[0] = t[2]; bl1[1] = t[3];
                mma16816(oacc[nj*2], aPh, bh0);   mma16816(oacc[nj*2+1], aPh, bh1);
                mma16816(oacc[nj*2], aPh, bl0);   mma16816(oacc[nj*2+1], aPh, bl1);
                mma16816(oacc[nj*2], aPl, bh0);   mma16816(oacc[nj*2+1], aPl, bh1);
            }
        }
        if (more) cp_wait0();
        __syncthreads();
    }

    // epilogue: token-major bf16 planes
    float li[2] = {1.f / lrun[0], 1.f / lrun[1]};
    #pragma unroll
    for (int nt = 0; nt < 8; nt++)
        #pragma unroll
        for (int r = 0; r < 2; r++) {
            int q = m0 + (lane >> 2) + r * 8;
            int d0 = nt * 8 + (lane & 3) * 2;
            unsigned hi, lo;
            splitpk(oacc[nt][2*r] * li[r], oacc[nt][2*r+1] * li[r], hi, lo);
            size_t idx = ((size_t)bimg * 1024 + q0 + q) * 256 + hoff + d0;
            *(unsigned*)(ohi + idx) = hi;
            *(unsigned*)(olo + idx) = lo;
        }
}

// ---------------- depthwise 3x3 + exact GELU ----------------
__global__ __launch_bounds__(256) void dwconv_gelu(
    const float* __restrict__ X, const float* __restrict__ W, float* __restrict__ Y)
{
    int idx = blockIdx.x * 256 + threadIdx.x;
    int x = idx & 31;
    int y = (idx >> 5) & 31;
    int c = (idx >> 10) & 1023;
    int b = idx >> 20;
    const float* xb = X + ((size_t)b * HIDDEN + c) * HW;
    const float* wc = W + c * 9;
    float acc = 0.f;
    #pragma unroll
    for (int dy = 0; dy < 3; dy++) {
        int iy = y + dy - 1;
        #pragma unroll
        for (int dx = 0; dx < 3; dx++) {
            int ix = x + dx - 1;
            if ((unsigned)iy < 32u && (unsigned)ix < 32u)
                acc += wc[dy * 3 + dx] * xb[(iy << 5) + ix];
        }
    }
    Y[idx] = 0.5f * acc * (1.f + erff(acc * 0.70710678118654752440f));
}

// ---------------- host ----------------
extern "C" void kernel_launch(void* const* d_in, const int* in_sizes, int n_in,
                              void* d_out, int out_size)
{
    const float* aop      = (const float*)d_in[0];
    const float* dop      = (const float*)d_in[1];
    const float* w_qconv  = (const float*)d_in[2];
    const float* w_kvconv = (const float*)d_in[3];
    const float* lnq1_w   = (const float*)d_in[4];
    const float* lnq1_b   = (const float*)d_in[5];
    const float* lnkv1_w  = (const float*)d_in[6];
    const float* lnkv1_b  = (const float*)d_in[7];
    const float* lnq2_w   = (const float*)d_in[8];
    const float* lnq2_b   = (const float*)d_in[9];
    const float* lnkv2_w  = (const float*)d_in[10];
    const float* lnkv2_b  = (const float*)d_in[11];
    const float* lnffn_w  = (const float*)d_in[12];
    const float* lnffn_b  = (const float*)d_in[13];
    const float* saq_qkv  = (const float*)d_in[14];
    const float* saq_proj = (const float*)d_in[15];
    const float* sakv_qkv = (const float*)d_in[16];
    const float* sakv_proj= (const float*)d_in[17];
    const float* ca_q     = (const float*)d_in[18];
    const float* ca_k     = (const float*)d_in[19];
    const float* ca_v     = (const float*)d_in[20];
    const float* ca_proj  = (const float*)d_in[21];
    const float* leff_in  = (const float*)d_in[22];
    const float* leff_dw  = (const float*)d_in[23];
    const float* leff_out = (const float*)d_in[24];
    float* out = (float*)d_out;

    float *qbr, *kvbr, *h1, *h2;
    __nv_bfloat16 *wbf, *bln, *bqk, *bv, *batt;
    cudaGetSymbolAddress((void**)&qbr,  g_qbranch);
    cudaGetSymbolAddress((void**)&kvbr, g_kvbranch);
    cudaGetSymbolAddress((void**)&h1,   g_h1);
    cudaGetSymbolAddress((void**)&h2,   g_h2);
    cudaGetSymbolAddress((void**)&wbf,  g_wbf);
    cudaGetSymbolAddress((void**)&bln,  g_bln);
    cudaGetSymbolAddress((void**)&bqk,  g_bqk);
    cudaGetSymbolAddress((void**)&bv,   g_bv);
    cudaGetSymbolAddress((void**)&batt, g_batt);

    __nv_bfloat16 *blnh = bln, *blnl = bln + 2097152;
    __nv_bfloat16 *bvh = bv, *bvl = bv + 2097152;
    __nv_bfloat16 *batth = batt, *battl = batt + 2097152;

    const int MM_SMEM = 131072;
    const int ATT_SMEM = 81920;
    cudaFuncSetAttribute(attn_mma, cudaFuncAttributeMaxDynamicSharedMemorySize, ATT_SMEM);
    cudaFuncSetAttribute(mm_tc<0,0,0>, cudaFuncAttributeMaxDynamicSharedMemorySize, MM_SMEM);
    cudaFuncSetAttribute(mm_tc<0,0,1>, cudaFuncAttributeMaxDynamicSharedMemorySize, MM_SMEM);
    cudaFuncSetAttribute(mm_tc<3,1,0>, cudaFuncAttributeMaxDynamicSharedMemorySize, MM_SMEM);
    cudaFuncSetAttribute(mm_tc<5,2,0>, cudaFuncAttributeMaxDynamicSharedMemorySize, MM_SMEM);

    // weight prep
    cvt_conv_w<<<(int)((SZ3+255)/256), 256>>>(wbf+OC3, wbf+OC3+SZ3, w_qconv, 9, (int)SZ3);
    cvt_conv_w<<<(int)((SZ5+255)/256), 256>>>(wbf+OC5, wbf+OC5+SZ5, w_kvconv, 25, (int)SZ5);
    cvt_w<<<(int)((SZQKV+255)/256), 256>>>(wbf+OSAQ,  wbf+OSAQ+SZQKV,  saq_qkv,  (int)SZQKV);
    cvt_w<<<(int)((SZQKV+255)/256), 256>>>(wbf+OSAKV, wbf+OSAKV+SZQKV, sakv_qkv, (int)SZQKV);
    cvt_w<<<(int)((SZCC+255)/256), 256>>>(wbf+OSAQP,  wbf+OSAQP+SZCC,  saq_proj, (int)SZCC);
    cvt_w<<<(int)((SZCC+255)/256), 256>>>(wbf+OSAKVP, wbf+OSAKVP+SZCC, sakv_proj,(int)SZCC);
    cvt_w<<<(int)((SZCC+255)/256), 256>>>(wbf+OCAQ, wbf+OCAQ+SZCC, ca_q, (int)SZCC);
    cvt_w<<<(int)((SZCC+255)/256), 256>>>(wbf+OCAK, wbf+OCAK+SZCC, ca_k, (int)SZCC);
    cvt_w<<<(int)((SZCC+255)/256), 256>>>(wbf+OCAV, wbf+OCAV+SZCC, ca_v, (int)SZCC);
    cvt_w<<<(int)((SZCC+255)/256), 256>>>(wbf+OCAP, wbf+OCAP+SZCC, ca_proj, (int)SZCC);
    cvt_w<<<(int)((SZLF+255)/256), 256>>>(wbf+OLIN,  wbf+OLIN+SZLF,  leff_in,  (int)SZLF);
    cvt_w<<<(int)((SZLF+255)/256), 256>>>(wbf+OLOUT, wbf+OLOUT+SZLF, leff_out, (int)SZLF);

    dim3 gC(8, 2, NB), gQK(8, 4, NB), gV(8, 2, NB), gHID(8, 8, NB);
    dim3 gLN(32, NB), gATT(16, 4, NB);
    const __nv_bfloat16* wsaq = wbf + OSAQ;
    const __nv_bfloat16* wsakv = wbf + OSAKV;

    // ---- q branch ----
    mm_tc<3,1,0><<<gC, 256, MM_SMEM>>>(wbf+OC3, wbf+OC3+SZ3, aop, nullptr, nullptr, 0,
                                       qbr, nullptr, nullptr, nullptr, 2304, 256, 256, 0);
    ln_kernel<<<gLN, 256>>>(qbr, lnq1_w, lnq1_b, blnh, blnl);
    mm_tc<0,0,1><<<gQK, 256, MM_SMEM>>>(wsaq, wsaq + SZQKV, nullptr, blnh, blnl, 256,
                                        nullptr, nullptr, bqk, bqk + 4194304, 256, 0, 512, 1);
    mm_tc<0,0,1><<<gV, 256, MM_SMEM>>>(wsaq + 512*256, wsaq + SZQKV + 512*256, nullptr, blnh, blnl, 256,
                                       nullptr, nullptr, bvh, bvl, 256, 0, 256, 2);
    attn_mma<<<gATT, 128, ATT_SMEM>>>(bqk, bqk + 4194304, 512,
                                      bqk + 256, bqk + 4194304 + 256, 512,
                                      bvh, bvl, batth, battl);
    mm_tc<0,0,1><<<gC, 256, MM_SMEM>>>(wbf+OSAQP, wbf+OSAQP+SZCC, nullptr, batth, battl, 256,
                                       qbr, qbr, nullptr, nullptr, 256, 0, 256, 0);

    // ---- kv branch ----
    mm_tc<5,2,0><<<gC, 256, MM_SMEM>>>(wbf+OC5, wbf+OC5+SZ5, dop, nullptr, nullptr, 0,
                                       kvbr, nullptr, nullptr, nullptr, 6400, 256, 256, 0);
    ln_kernel<<<gLN, 256>>>(kvbr, lnkv1_w, lnkv1_b, blnh, blnl);
    mm_tc<0,0,1><<<gQK, 256, MM_SMEM>>>(wsakv, wsakv + SZQKV, nullptr, blnh, blnl, 256,
                                        nullptr, nullptr, bqk, bqk + 4194304, 256, 0, 512, 1);
    mm_tc<0,0,1><<<gV, 256, MM_SMEM>>>(wsakv + 512*256, wsakv + SZQKV + 512*256, nullptr, blnh, blnl, 256,
                                       nullptr, nullptr, bvh, bvl, 256, 0, 256, 2);
    attn_mma<<<gATT, 128, ATT_SMEM>>>(bqk, bqk + 4194304, 512,
                                      bqk + 256, bqk + 4194304 + 256, 512,
                                      bvh, bvl, batth, battl);
    mm_tc<0,0,1><<<gC, 256, MM_SMEM>>>(wbf+OSAKVP, wbf+OSAKVP+SZCC, nullptr, batth, battl, 256,
                                       kvbr, kvbr, nullptr, nullptr, 256, 0, 256, 0);

    // ---- cross attention ----
    ln_kernel<<<gLN, 256>>>(qbr, lnq2_w, lnq2_b, blnh, blnl);
    mm_tc<0,0,1><<<gV, 256, MM_SMEM>>>(wbf+OCAQ, wbf+OCAQ+SZCC, nullptr, blnh, blnl, 256,
                                       nullptr, nullptr, bqk, bqk + 2097152, 256, 0, 256, 1);
    ln_kernel<<<gLN, 256>>>(kvbr, lnkv2_w, lnkv2_b, blnh, blnl);
    mm_tc<0,0,1><<<gV, 256, MM_SMEM>>>(wbf+OCAK, wbf+OCAK+SZCC, nullptr, blnh, blnl, 256,
                                       nullptr, nullptr, bqk + 4194304, bqk + 6291456, 256, 0, 256, 1);
    mm_tc<0,0,1><<<gV, 256, MM_SMEM>>>(wbf+OCAV, wbf+OCAV+SZCC, nullptr, blnh, blnl, 256,
                                       nullptr, nullptr, bvh, bvl, 256, 0, 256, 2);
    attn_mma<<<gATT, 128, ATT_SMEM>>>(bqk, bqk + 2097152, 256,
                                      bqk + 4194304, bqk + 6291456, 256,
                                      bvh, bvl, batth, battl);
    mm_tc<0,0,1><<<gC, 256, MM_SMEM>>>(wbf+OCAP, wbf+OCAP+SZCC, nullptr, batth, battl, 256,
                                       out, qbr, nullptr, nullptr, 256, 0, 256, 0);

    // ---- LeFF ----
    ln_kernel<<<gLN, 256>>>(out, lnffn_w, lnffn_b, blnh, blnl);
    mm_tc<0,0,1><<<gHID, 256, MM_SMEM>>>(wbf+OLIN, wbf+OLIN+SZLF, nullptr, blnh, blnl, 256,
                                         h1, nullptr, nullptr, nullptr, 256, 0, 1024, 0);
    dwconv_gelu<<<(NB * HIDDEN * HW) / 256, 256>>>(h1, leff_dw, h2);
    mm_tc<0,0,0><<<gC, 256, MM_SMEM>>>(wbf+OLOUT, wbf+OLOUT+SZLF, h2, nullptr, nullptr, 0,
                                       out, out, nullptr, nullptr, 1024, 1024, 256, 0);
}

// round 12
// speedup vs baseline: 2.5128x; 1.0170x over previous
#include <cuda_runtime.h>
#include <cuda_bf16.h>
#include <math.h>
#include <stdint.h>

#define NB 8
#define C 256
#define HW 1024
#define HIDDEN 1024

__device__ float g_qbranch[NB*C*HW];
__device__ float g_kvbranch[NB*C*HW];
__device__ float g_h1[NB*HIDDEN*HW];
__device__ float g_h2[NB*HIDDEN*HW];            // reused as bf16 tokmaj planes after dwconv
__device__ __align__(256) __nv_bfloat16 g_wbf[7100000];
__device__ __align__(256) __nv_bfloat16 g_bln[4194304];   // 2 planes x (8,1024,256)
__device__ __align__(256) __nv_bfloat16 g_bqk[8388608];   // 2 planes x (8,1024,512) or ca q/k
__device__ __align__(256) __nv_bfloat16 g_bv[4194304];    // 2 planes x (8,256,1024)
__device__ __align__(256) __nv_bfloat16 g_batt[4194304];  // 2 planes x (8,1024,256)

// weight layout (hi plane at off, lo plane at off+span)
#define WC3    0
#define SP3    589824
#define WC5    1179648
#define SP5    1638400
#define WSAQ   4456448
#define SPQKV  196608
#define WSAKV  4849664
#define WSAQP  5242880
#define SPCC   65536
#define WSAKVP 5373952
#define WCAQ   5505024
#define WCAKV  5636096
#define SPKV   131072
#define WCAP   5898240
#define WLIN   6029312
#define SPLF   262144
#define WLOUT  6553600

// ---------------- helpers ----------------
__device__ __forceinline__ uint32_t smem_u32(const void* p) {
    uint32_t a;
    asm("{ .reg .u64 t; cvta.to.shared.u64 t, %1; cvt.u32.u64 %0, t; }" : "=r"(a) : "l"(p));
    return a;
}
__device__ __forceinline__ void cp16(void* dst, const void* src) {
    unsigned d = (unsigned)__cvta_generic_to_shared(dst);
    asm volatile("cp.async.ca.shared.global [%0], [%1], 16;" :: "r"(d), "l"(src));
}
__device__ __forceinline__ void cp_commit() { asm volatile("cp.async.commit_group;" ::: "memory"); }
__device__ __forceinline__ void cp_wait0()  { asm volatile("cp.async.wait_group 0;" ::: "memory"); }

__device__ __forceinline__ void ldmx4(uint32_t* r, uint32_t addr) {
    asm volatile("ldmatrix.sync.aligned.m8n8.x4.shared.b16 {%0,%1,%2,%3}, [%4];"
        : "=r"(r[0]), "=r"(r[1]), "=r"(r[2]), "=r"(r[3]) : "r"(addr));
}
__device__ __forceinline__ void mma16816(float* c, const uint32_t* a, const uint32_t* b) {
    asm volatile("mma.sync.aligned.m16n8k16.row.col.f32.bf16.bf16.f32 "
        "{%0,%1,%2,%3}, {%4,%5,%6,%7}, {%8,%9}, {%0,%1,%2,%3};"
        : "+f"(c[0]), "+f"(c[1]), "+f"(c[2]), "+f"(c[3])
        : "r"(a[0]), "r"(a[1]), "r"(a[2]), "r"(a[3]), "r"(b[0]), "r"(b[1]));
}
__device__ __forceinline__ unsigned pkbf(float a, float b) {
    __nv_bfloat16 ha = __float2bfloat16(a), hb = __float2bfloat16(b);
    return ((unsigned)__bfloat16_as_ushort(hb) << 16) | __bfloat16_as_ushort(ha);
}
__device__ __forceinline__ void splitpk(float a, float b, unsigned& hi, unsigned& lo) {
    __nv_bfloat16 ha = __float2bfloat16(a), hb = __float2bfloat16(b);
    hi = ((unsigned)__bfloat16_as_ushort(hb) << 16) | __bfloat16_as_ushort(ha);
    lo = pkbf(a - __bfloat162float(ha), b - __bfloat162float(hb));
}

// =====================================================================
// mma.sync GEMM / implicit conv.
// ABF=0: act fp32 chanmaj [b][SA][1024] (KW taps for conv)
// ABF=1: pre-split bf16 A tokmaj rows of arow elems
// outmode 0: fp32 chanmaj (+addp); 1: bf16 tokmaj planes; 2: bf16 chanmaj planes;
// 3: y<ysplit -> tokmaj (obhi/oblo, row Cout), else chanmaj (vbhi/vblo, 256 rows)
// =====================================================================
template<int KW, int PAD, int ABF>
__global__ __launch_bounds__(256, 1) void mm_tc(
    const __nv_bfloat16* __restrict__ whi, const __nv_bfloat16* __restrict__ wlo,
    const float* __restrict__ act,
    const __nv_bfloat16* __restrict__ ahi, const __nv_bfloat16* __restrict__ alo, int arow,
    float* __restrict__ outp, const float* __restrict__ addp,
    __nv_bfloat16* __restrict__ obhi, __nv_bfloat16* __restrict__ oblo,
    __nv_bfloat16* __restrict__ vbhi, __nv_bfloat16* __restrict__ vblo,
    int K, int SA, int Cout, int outmode, int ysplit)
{
    extern __shared__ char sm[];
    int tid = threadIdx.x;
    int pixbase = blockIdx.x * 128;
    int ocbase = blockIdx.y * 128;
    int bimg = blockIdx.z;
    int w = tid >> 5, lane = tid & 31;
    int m0 = (w >> 1) * 32;
    int n0 = (w & 1) * 64;
    uint32_t sbase = smem_u32(sm);

    float acc[2][8][4] = {};
    int apix = tid & 127, ahalf = tid >> 7;

    auto fetchA = [&](int kk, float* v) {
        if (KW == 0) {
            const float* p = act + ((size_t)bimg * SA + kk + ahalf * 32) * 1024 + pixbase + apix;
            #pragma unroll
            for (int i = 0; i < 32; i++) v[i] = p[(size_t)i * 1024];
        } else {
            int kbase = kk + ahalf * 32;
            int tap = kbase >> 8, ic0 = kbase & 255;
            int dy = tap / KW - PAD, dx = tap % KW - PAD;
            int p = pixbase + apix;
            int iy = (p >> 5) + dy, ix = (p & 31) + dx;
            bool ok = ((unsigned)iy < 32u) && ((unsigned)ix < 32u);
            const float* src = act + ((size_t)bimg * 256 + ic0) * 1024 + (iy << 5) + ix;
            #pragma unroll
            for (int i = 0; i < 32; i++) v[i] = ok ? src[(size_t)i * 1024] : 0.f;
        }
    };
    auto storeA = [&](int st, const float* v) {
        char* AH = sm + st * 65536;
        char* AL = AH + 16384;
        #pragma unroll
        for (int gi = 0; gi < 4; gi++) {
            int g = ahalf * 4 + gi;
            unsigned hh[4], ll[4];
            #pragma unroll
            for (int m = 0; m < 4; m++)
                splitpk(v[gi * 8 + 2 * m], v[gi * 8 + 2 * m + 1], hh[m], ll[m]);
            unsigned off = apix * 128 + ((g ^ (apix & 7)) << 4);
            *(uint4*)(AH + off) = make_uint4(hh[0], hh[1], hh[2], hh[3]);
            *(uint4*)(AL + off) = make_uint4(ll[0], ll[1], ll[2], ll[3]);
        }
    };
    auto loadAbf = [&](int st, int kk) {
        char* base = sm + st * 65536;
        #pragma unroll
        for (int i = 0; i < 8; i++) {
            int idx = tid + i * 256;
            int plane = idx >> 10, r = idx & 1023;
            int pix = r >> 3, g = r & 7;
            const __nv_bfloat16* src = (plane ? alo : ahi)
                + ((size_t)bimg * 1024 + pixbase + pix) * arow + kk + g * 8;
            unsigned off = pix * 128 + ((g ^ (pix & 7)) << 4);
            cp16(base + plane * 16384 + off, src);
        }
    };
    auto loadB = [&](int st, int kk) {
        char* base = sm + st * 65536 + 32768;
        #pragma unroll
        for (int i = 0; i < 8; i++) {
            int idx = tid + i * 256;
            int plane = idx >> 10, r = idx & 1023;
            int oc = r >> 3, g = r & 7;
            const __nv_bfloat16* src = (plane ? wlo : whi) + (size_t)(ocbase + oc) * K + kk + g * 8;
            unsigned off = oc * 128 + ((g ^ (oc & 7)) << 4);
            cp16(base + plane * 16384 + off, src);
        }
    };
    auto compute = [&](int st) {
        uint32_t AH = sbase + st * 65536, AL = AH + 16384;
        uint32_t BH = AH + 32768, BL = AH + 49152;
        #pragma unroll
        for (int ks = 0; ks < 4; ks++) {
            int kg = ks * 2;
            uint32_t aH[2][4], aL[2][4], bH[8][2], bL[8][2];
            #pragma unroll
            for (int ms = 0; ms < 2; ms++) {
                int sel = lane >> 3;
                int row = m0 + ms * 16 + (sel & 1) * 8 + (lane & 7);
                int g = kg + (sel >> 1);
                unsigned off = row * 128 + ((g ^ (row & 7)) << 4);
                ldmx4(aH[ms], AH + off);
                ldmx4(aL[ms], AL + off);
            }
            #pragma unroll
            for (int nj = 0; nj < 4; nj++) {
                int j2 = lane >> 4, half = (lane >> 3) & 1;
                int oc = n0 + (nj * 2 + j2) * 8 + (lane & 7);
                int g = kg + half;
                unsigned off = oc * 128 + ((g ^ (oc & 7)) << 4);
                uint32_t t[4];
                ldmx4(t, BH + off);
                bH[nj*2][0] = t[0]; bH[nj*2][1] = t[1]; bH[nj*2+1][0] = t[2]; bH[nj*2+1][1] = t[3];
                ldmx4(t, BL + off);
                bL[nj*2][0] = t[0]; bL[nj*2][1] = t[1]; bL[nj*2+1][0] = t[2]; bL[nj*2+1][1] = t[3];
            }
            #pragma unroll
            for (int ms = 0; ms < 2; ms++)
                #pragma unroll
                for (int ns = 0; ns < 8; ns++) {
                    mma16816(acc[ms][ns], aH[ms], bH[ns]);
                    mma16816(acc[ms][ns], aH[ms], bL[ns]);
                    mma16816(acc[ms][ns], aL[ms], bH[ns]);
                }
        }
    };

    int nk = K >> 6;
    if (ABF) {
        loadB(0, 0); loadAbf(0, 0);
        cp_commit();
        cp_wait0();
        __syncthreads();
        for (int kt = 0; kt < nk; kt++) {
            int st = kt & 1;
            bool more = (kt + 1) < nk;
            if (more) {
                loadB(st ^ 1, (kt + 1) << 6);
                loadAbf(st ^ 1, (kt + 1) << 6);
                cp_commit();
            }
            compute(st);
            if (more) cp_wait0();
            __syncthreads();
        }
    } else {
        float v[32];
        loadB(0, 0); cp_commit();
        fetchA(0, v); storeA(0, v);
        cp_wait0();
        __syncthreads();
        for (int kt = 0; kt < nk; kt++) {
            int st = kt & 1;
            bool more = (kt + 1) < nk;
            if (more) {
                loadB(st ^ 1, (kt + 1) << 6); cp_commit();
                fetchA((kt + 1) << 6, v);
            }
            compute(st);
            if (more) {
                storeA(st ^ 1, v);
                cp_wait0();
            }
            __syncthreads();
        }
    }

    // output-mode resolution (outmode 3 splits by blockIdx.y)
    int outm = outmode;
    int ocb = ocbase;
    __nv_bfloat16 *ph = obhi, *pl = oblo;
    if (outmode == 3) {
        if ((int)blockIdx.y < ysplit) outm = 1;
        else { outm = 2; ph = vbhi; pl = vblo; ocb = (blockIdx.y - ysplit) * 128; }
    }

    float* T = (float*)sm;   // [128][132]
    if (outm == 1) {
        #pragma unroll
        for (int ms = 0; ms < 2; ms++)
            #pragma unroll
            for (int ns = 0; ns < 8; ns++)
                #pragma unroll
                for (int e = 0; e < 4; e++) {
                    int pix = m0 + ms * 16 + (lane >> 2) + (e >> 1) * 8;
                    int oc  = n0 + ns * 8 + (lane & 3) * 2 + (e & 1);
                    T[pix * 132 + oc] = acc[ms][ns][e];
                }
        __syncthreads();
        #pragma unroll
        for (int it = 0; it < 16; it++) {
            int f = it * 256 + tid;
            int pix = f >> 5, o4 = (f & 31) * 4;
            float4 vv = *(float4*)&T[pix * 132 + o4];
            unsigned h0, l0, h1, l1;
            splitpk(vv.x, vv.y, h0, l0);
            splitpk(vv.z, vv.w, h1, l1);
            size_t idx = ((size_t)bimg * 1024 + pixbase + pix) * Cout + ocbase + o4;
            *(uint2*)(ph + idx) = make_uint2(h0, h1);
            *(uint2*)(pl + idx) = make_uint2(l0, l1);
        }
    } else {
        #pragma unroll
        for (int ms = 0; ms < 2; ms++)
            #pragma unroll
            for (int ns = 0; ns < 8; ns++)
                #pragma unroll
                for (int e = 0; e < 4; e++) {
                    int pix = m0 + ms * 16 + (lane >> 2) + (e >> 1) * 8;
                    int oc  = n0 + ns * 8 + (lane & 3) * 2 + (e & 1);
                    T[oc * 132 + pix] = acc[ms][ns][e];
                }
        __syncthreads();
        #pragma unroll
        for (int it = 0; it < 16; it++) {
            int f = it * 256 + tid;
            int oc = f >> 5, p4 = (f & 31) * 4;
            float4 vv = *(float4*)&T[oc * 132 + p4];
            if (outm == 0) {
                size_t go = ((size_t)bimg * Cout + ocb + oc) * 1024 + pixbase + p4;
                if (addp) {
                    float4 a = *(const float4*)(addp + go);
                    vv.x += a.x; vv.y += a.y; vv.z += a.z; vv.w += a.w;
                }
                *(float4*)(outp + go) = vv;
            } else {
                unsigned h0, l0, h1, l1;
                splitpk(vv.x, vv.y, h0, l0);
                splitpk(vv.z, vv.w, h1, l1);
                size_t idx = ((size_t)bimg * 256 + ocb + oc) * 1024 + pixbase + p4;
                *(uint2*)(ph + idx) = make_uint2(h0, h1);
                *(uint2*)(pl + idx) = make_uint2(l0, l1);
            }
        }
    }
}

// ---------------- fused weight prep (all 12 conversions, one launch) ----------------
__global__ __launch_bounds__(256) void prep_w(
    __nv_bfloat16* __restrict__ wb,
    const float* w3, const float* w5,
    const float* saqk, const float* sakvk,
    const float* saqp, const float* sakvp,
    const float* caq, const float* cak, const float* cav, const float* cap,
    const float* lin, const float* lout)
{
    int i = blockIdx.x * 256 + threadIdx.x;
    float v; size_t dh, dl;
    if (i < 589824) {                                  // conv3 reorder [oc][ic][9]->[oc][t][ic]
        int j = i;
        int oc = j / (9*256); int r = j - oc*9*256; int tap = r >> 8, ic = r & 255;
        v = w3[((size_t)(oc*256+ic))*9 + tap]; dh = WC3 + j; dl = dh + SP3;
    } else if (i < 2228224) {                          // conv5
        int j = i - 589824;
        int oc = j / (25*256); int r = j - oc*25*256; int tap = r >> 8, ic = r & 255;
        v = w5[((size_t)(oc*256+ic))*25 + tap]; dh = WC5 + j; dl = dh + SP5;
    } else if (i < 2424832) { int j = i - 2228224; v = saqk[j];  dh = WSAQ + j;  dl = dh + SPQKV; }
    else if (i < 2621440) { int j = i - 2424832; v = sakvk[j]; dh = WSAKV + j; dl = dh + SPQKV; }
    else if (i < 2686976) { int j = i - 2621440; v = saqp[j];  dh = WSAQP + j; dl = dh + SPCC; }
    else if (i < 2752512) { int j = i - 2686976; v = sakvp[j]; dh = WSAKVP + j; dl = dh + SPCC; }
    else if (i < 2818048) { int j = i - 2752512; v = caq[j];   dh = WCAQ + j;  dl = dh + SPCC; }
    else if (i < 2883584) { int j = i - 2818048; v = cak[j];   dh = WCAKV + j; dl = dh + SPKV; }
    else if (i < 2949120) { int j = i - 2883584; v = cav[j];   dh = WCAKV + 65536 + j; dl = dh + SPKV; }
    else if (i < 3014656) { int j = i - 2949120; v = cap[j];   dh = WCAP + j;  dl = dh + SPCC; }
    else if (i < 3276800) { int j = i - 3014656; v = lin[j];   dh = WLIN + j;  dl = dh + SPLF; }
    else if (i < 3538944) { int j = i - 3276800; v = lout[j];  dh = WLOUT + j; dl = dh + SPLF; }
    else return;
    __nv_bfloat16 h = __float2bfloat16(v);
    wb[dh] = h;
    wb[dl] = __float2bfloat16(v - __bfloat162float(h));
}

// ---------------- layernorm: chanmaj fp32 -> tokmaj bf16 hi/lo planes ----------------
__global__ __launch_bounds__(256) void ln_kernel(
    const float* __restrict__ x, const float* __restrict__ w,
    const float* __restrict__ bias,
    __nv_bfloat16* __restrict__ bhi, __nv_bfloat16* __restrict__ blo)
{
    int b = blockIdx.y;
    int n0 = blockIdx.x * 32;
    int nx = threadIdx.x & 31;
    int cg = threadIdx.x >> 5;
    const float* xb = x + (size_t)b * C * HW + n0 + nx;
    float v[32];
    float s = 0.f, ss = 0.f;
    #pragma unroll
    for (int i = 0; i < 32; i++) {
        float t = xb[(size_t)(cg * 32 + i) * HW];
        v[i] = t; s += t; ss += t * t;
    }
    __shared__ float rs[8][32], rss[8][32];
    rs[cg][nx] = s; rss[cg][nx] = ss;
    __syncthreads();
    float tot = 0.f, tot2 = 0.f;
    #pragma unroll
    for (int g = 0; g < 8; g++) { tot += rs[g][nx]; tot2 += rss[g][nx]; }
    float mu = tot * (1.f / 256.f);
    float var = tot2 * (1.f / 256.f) - mu * mu;
    float rstd = rsqrtf(var + 1e-5f);
    size_t orow = ((size_t)b * 1024 + n0 + nx) * 256 + cg * 32;
    #pragma unroll
    for (int i4 = 0; i4 < 4; i4++) {
        unsigned hh[4], ll[4];
        #pragma unroll
        for (int j = 0; j < 4; j++) {
            int i = i4 * 8 + j * 2;
            int c = cg * 32 + i;
            float a = (v[i]   - mu) * rstd * w[c]   + bias[c];
            float d = (v[i+1] - mu) * rstd * w[c+1] + bias[c+1];
            splitpk(a, d, hh[j], ll[j]);
        }
        *(uint4*)(bhi + orow + i4 * 8) = make_uint4(hh[0], hh[1], hh[2], hh[3]);
        *(uint4*)(blo + orow + i4 * 8) = make_uint4(ll[0], ll[1], ll[2], ll[3]);
    }
}

// ---------------- tensor-core flash attention (pre-split bf16) ----------------
__global__ __launch_bounds__(128) void attn_mma(
    const __nv_bfloat16* __restrict__ qhi, const __nv_bfloat16* __restrict__ qlo, int qrow,
    const __nv_bfloat16* __restrict__ khi, const __nv_bfloat16* __restrict__ klo, int krow,
    const __nv_bfloat16* __restrict__ vhi, const __nv_bfloat16* __restrict__ vlo,
    __nv_bfloat16* __restrict__ ohi, __nv_bfloat16* __restrict__ olo)
{
    extern __shared__ char sm[];
    uint32_t sbase = smem_u32(sm);
    int tid = threadIdx.x;
    int w = tid >> 5, lane = tid & 31;
    int q0 = blockIdx.x * 64;
    int hoff = blockIdx.y * 64;
    int bimg = blockIdx.z;
    int m0 = w * 16;

    auto loadQ = [&]() {
        #pragma unroll
        for (int i = 0; i < 8; i++) {
            int idx = tid + i * 128;
            int plane = idx >> 9, r = idx & 511;
            int q = r >> 3, g = r & 7;
            const __nv_bfloat16* src = (plane ? qlo : qhi)
                + ((size_t)bimg * 1024 + q0 + q) * qrow + hoff + g * 8;
            unsigned off = q * 128 + ((g ^ (q & 7)) << 4);
            cp16(sm + plane * 8192 + off, src);
        }
    };
    auto loadKV = [&](int st, int c0) {
        char* base = sm + 16384 + st * 32768;
        #pragma unroll
        for (int i = 0; i < 16; i++) {
            int idx = tid + i * 128;
            int which = idx >> 10;
            int plane = (idx >> 9) & 1;
            int r = idx & 511;
            int row = r >> 3, g = r & 7;
            const __nv_bfloat16* src;
            if (which == 0)
                src = (plane ? klo : khi) + ((size_t)bimg * 1024 + c0 + row) * krow + hoff + g * 8;
            else
                src = (plane ? vlo : vhi) + ((size_t)bimg * 256 + hoff + row) * 1024 + c0 + g * 8;
            unsigned off = row * 128 + ((g ^ (row & 7)) << 4);
            cp16(base + which * 16384 + plane * 8192 + off, src);
        }
    };

    loadQ();
    loadKV(0, 0);
    cp_commit();

    float oacc[8][4] = {};
    float mrun[2], lrun[2];
    mrun[0] = mrun[1] = -1e30f;
    lrun[0] = lrun[1] = 0.f;

    cp_wait0();
    __syncthreads();

    const uint32_t QH = sbase, QL = sbase + 8192;
    for (int c = 0; c < 16; c++) {
        int st = c & 1;
        bool more = (c + 1) < 16;
        if (more) { loadKV(st ^ 1, (c + 1) * 64); cp_commit(); }

        uint32_t KB = sbase + 16384 + st * 32768;
        uint32_t KH = KB, KL = KB + 8192, VH = KB + 16384, VL = KB + 24576;

        float s[8][4] = {};
        #pragma unroll
        for (int ks4 = 0; ks4 < 4; ks4++) {
            int kg = ks4 * 2;
            uint32_t aH[4], aL[4];
            {
                int sel = lane >> 3;
                int row = m0 + (sel & 1) * 8 + (lane & 7);
                int g = kg + (sel >> 1);
                unsigned off = row * 128 + ((g ^ (row & 7)) << 4);
                ldmx4(aH, QH + off);
                ldmx4(aL, QL + off);
            }
            #pragma unroll
            for (int nj = 0; nj < 4; nj++) {
                int j2 = lane >> 4, half = (lane >> 3) & 1;
                int kv = (nj * 2 + j2) * 8 + (lane & 7);
                int g = kg + half;
                unsigned off = kv * 128 + ((g ^ (kv & 7)) << 4);
                uint32_t t[4], bh0[2], bh1[2], bl0[2], bl1[2];
                ldmx4(t, KH + off);
                bh0[0] = t[0]; bh0[1] = t[1]; bh1[0] = t[2]; bh1[1] = t[3];
                ldmx4(t, KL + off);
                bl0[0] = t[0]; bl0[1] = t[1]; bl1[0] = t[2]; bl1[1] = t[3];
                mma16816(s[nj*2], aH, bh0);   mma16816(s[nj*2+1], aH, bh1);
                mma16816(s[nj*2], aH, bl0);   mma16816(s[nj*2+1], aH, bl1);
                mma16816(s[nj*2], aL, bh0);   mma16816(s[nj*2+1], aL, bh1);
            }
        }
        #pragma unroll
        for (int e = 0; e < 8; e++)
            #pragma unroll
            for (int j = 0; j < 4; j++) s[e][j] *= 0.125f;

        #pragma unroll
        for (int r = 0; r < 2; r++) {
            int e0 = r * 2;
            float mx = -1e30f;
            #pragma unroll
            for (int e = 0; e < 8; e++)
                mx = fmaxf(mx, fmaxf(s[e][e0], s[e][e0+1]));
            mx = fmaxf(mx, __shfl_xor_sync(0xffffffffu, mx, 1));
            mx = fmaxf(mx, __shfl_xor_sync(0xffffffffu, mx, 2));
            float mnew = fmaxf(mrun[r], mx);
            float corr = __expf(mrun[r] - mnew);
            float rsum = 0.f;
            #pragma unroll
            for (int e = 0; e < 8; e++) {
                float p0 = __expf(s[e][e0] - mnew);
                float p1 = __expf(s[e][e0+1] - mnew);
                s[e][e0] = p0; s[e][e0+1] = p1;
                rsum += p0 + p1;
            }
            rsum += __shfl_xor_sync(0xffffffffu, rsum, 1);
            rsum += __shfl_xor_sync(0xffffffffu, rsum, 2);
            lrun[r] = lrun[r] * corr + rsum;
            mrun[r] = mnew;
            #pragma unroll
            for (int e = 0; e < 8; e++) {
                oacc[e][e0] *= corr; oacc[e][e0+1] *= corr;
            }
        }

        #pragma unroll
        for (int ks4 = 0; ks4 < 4; ks4++) {
            int e = ks4 * 2;
            uint32_t aPh[4], aPl[4];
            splitpk(s[e][0],   s[e][1],   aPh[0], aPl[0]);
            splitpk(s[e][2],   s[e][3],   aPh[1], aPl[1]);
            splitpk(s[e+1][0], s[e+1][1], aPh[2], aPl[2]);
            splitpk(s[e+1][2], s[e+1][3], aPh[3], aPl[3]);
            int kg = ks4 * 2;
            #pragma unroll
            for (int nj = 0; nj < 4; nj++) {
                int j2 = lane >> 4, half = (lane >> 3) & 1;
                int d = (nj * 2 + j2) * 8 + (lane & 7);
                int g = kg + half;
                unsigned off = d * 128 + ((g ^ (d & 7)) << 4);
                uint32_t t[4], bh0[2], bh1[2], bl0[2], bl1[2];
                ldmx4(t, VH + off);
                bh0[0] = t[0]; bh0[1] = t[1]; bh1[0] = t[2]; bh1[1] = t[3];
                ldmx4(t, VL + off);
                bl0[0] = t[0]; bl0[1] = t[1]; bl1[0] = t[2]; bl1[1] = t[3];
                mma16816(oacc[nj*2], aPh, bh0);   mma16816(oacc[nj*2+1], aPh, bh1);
                mma16816(oacc[nj*2], aPh, bl0);   mma16816(oacc[nj*2+1], aPh, bl1);
                mma16816(oacc[nj*2], aPl, bh0);   mma16816(oacc[nj*2+1], aPl, bh1);
            }
        }
        if (more) cp_wait0();
        __syncthreads();
    }

    float li[2] = {1.f / lrun[0], 1.f / lrun[1]};
    #pragma unroll
    for (int nt = 0; nt < 8; nt++)
        #pragma unroll
        for (int r = 0; r < 2; r++) {
            int q = m0 + (lane >> 2) + r * 8;
            int d0 = nt * 8 + (lane & 3) * 2;
            unsigned hi, lo;
            splitpk(oacc[nt][2*r] * li[r], oacc[nt][2*r+1] * li[r], hi, lo);
            size_t idx = ((size_t)bimg * 1024 + q0 + q) * 256 + hoff + d0;
            *(unsigned*)(ohi + idx) = hi;
            *(unsigned*)(olo + idx) = lo;
        }
}

// ---------------- depthwise 3x3 + GELU -> token-major bf16 hi/lo planes ----------------
// grid (4 pixtiles of 256, 32 cgroups of 32, 8 b), 256 threads
__global__ __launch_bounds__(256) void dwconv_gelu_tok(
    const float* __restrict__ X, const float* __restrict__ W,
    __nv_bfloat16* __restrict__ bhi, __nv_bfloat16* __restrict__ blo)
{
    __shared__ float tile[32][10][32];
    __shared__ float wsm[32][9];
    int tid = threadIdx.x;
    int p0 = blockIdx.x * 256;
    int c0 = blockIdx.y * 32;
    int b = blockIdx.z;
    int r0 = p0 >> 5;                       // starting image row of this pixtile

    // load weights (288 entries, 256 threads -> grid-stride)
    for (int e = tid; e < 288; e += 256) {
        int c = e / 9, k = e - c * 9;
        wsm[c][k] = W[(size_t)(c0 + c) * 9 + k];
    }
    // load input tile with row halo
    for (int e = tid; e < 32 * 10 * 32; e += 256) {
        int c = e / 320, rr = e - c * 320;
        int lr = rr >> 5, col = rr & 31;
        int gr = r0 + lr - 1;
        tile[c][lr][col] = ((unsigned)gr < 32u)
            ? X[((size_t)(b * 1024 + c0 + c)) * 1024 + (gr << 5) + col] : 0.f;
    }
    __syncthreads();

    int p = p0 + tid;
    int ly = (p >> 5) - r0 + 1;             // 1..8
    int x = p & 31;
    unsigned hh[16], ll[16];
    float prev = 0.f;
    #pragma unroll
    for (int c = 0; c < 32; c++) {
        float acc = 0.f;
        #pragma unroll
        for (int dy = 0; dy < 3; dy++) {
            #pragma unroll
            for (int dx = 0; dx < 3; dx++) {
                int ix = x + dx - 1;
                float vv = ((unsigned)ix < 32u) ? tile[c][ly + dy - 1][ix] : 0.f;
                acc += wsm[c][dy * 3 + dx] * vv;
            }
        }
        float g = 0.5f * acc * (1.f + erff(acc * 0.70710678118654752440f));
        if (c & 1) splitpk(prev, g, hh[c >> 1], ll[c >> 1]);
        prev = g;
    }
    size_t orow = ((size_t)b * 1024 + p) * 1024 + c0;
    #pragma unroll
    for (int q = 0; q < 4; q++) {
        *(uint4*)(bhi + orow + q * 8) = make_uint4(hh[q*4], hh[q*4+1], hh[q*4+2], hh[q*4+3]);
        *(uint4*)(blo + orow + q * 8) = make_uint4(ll[q*4], ll[q*4+1], ll[q*4+2], ll[q*4+3]);
    }
}

// ---------------- host ----------------
extern "C" void kernel_launch(void* const* d_in, const int* in_sizes, int n_in,
                              void* d_out, int out_size)
{
    const float* aop      = (const float*)d_in[0];
    const float* dop      = (const float*)d_in[1];
    const float* w_qconv  = (const float*)d_in[2];
    const float* w_kvconv = (const float*)d_in[3];
    const float* lnq1_w   = (const float*)d_in[4];
    const float* lnq1_b   = (const float*)d_in[5];
    const float* lnkv1_w  = (const float*)d_in[6];
    const float* lnkv1_b  = (const float*)d_in[7];
    const float* lnq2_w   = (const float*)d_in[8];
    const float* lnq2_b   = (const float*)d_in[9];
    const float* lnkv2_w  = (const float*)d_in[10];
    const float* lnkv2_b  = (const float*)d_in[11];
    const float* lnffn_w  = (const float*)d_in[12];
    const float* lnffn_b  = (const float*)d_in[13];
    const float* saq_qkv  = (const float*)d_in[14];
    const float* saq_proj = (const float*)d_in[15];
    const float* sakv_qkv = (const float*)d_in[16];
    const float* sakv_proj= (const float*)d_in[17];
    const float* ca_q     = (const float*)d_in[18];
    const float* ca_k     = (const float*)d_in[19];
    const float* ca_v     = (const float*)d_in[20];
    const float* ca_proj  = (const float*)d_in[21];
    const float* leff_in  = (const float*)d_in[22];
    const float* leff_dw  = (const float*)d_in[23];
    const float* leff_out = (const float*)d_in[24];
    float* out = (float*)d_out;

    float *qbr, *kvbr, *h1, *h2;
    __nv_bfloat16 *wbf, *bln, *bqk, *bv, *batt;
    cudaGetSymbolAddress((void**)&qbr,  g_qbranch);
    cudaGetSymbolAddress((void**)&kvbr, g_kvbranch);
    cudaGetSymbolAddress((void**)&h1,   g_h1);
    cudaGetSymbolAddress((void**)&h2,   g_h2);
    cudaGetSymbolAddress((void**)&wbf,  g_wbf);
    cudaGetSymbolAddress((void**)&bln,  g_bln);
    cudaGetSymbolAddress((void**)&bqk,  g_bqk);
    cudaGetSymbolAddress((void**)&bv,   g_bv);
    cudaGetSymbolAddress((void**)&batt, g_batt);

    __nv_bfloat16 *blnh = bln, *blnl = bln + 2097152;
    __nv_bfloat16 *bvh = bv, *bvl = bv + 2097152;
    __nv_bfloat16 *batth = batt, *battl = batt + 2097152;
    __nv_bfloat16 *dwh = (__nv_bfloat16*)h2, *dwl = (__nv_bfloat16*)h2 + 8388608;

    const int MM_SMEM = 131072;
    const int ATT_SMEM = 81920;
    cudaFuncSetAttribute(attn_mma, cudaFuncAttributeMaxDynamicSharedMemorySize, ATT_SMEM);
    cudaFuncSetAttribute(mm_tc<0,0,0>, cudaFuncAttributeMaxDynamicSharedMemorySize, MM_SMEM);
    cudaFuncSetAttribute(mm_tc<0,0,1>, cudaFuncAttributeMaxDynamicSharedMemorySize, MM_SMEM);
    cudaFuncSetAttribute(mm_tc<3,1,0>, cudaFuncAttributeMaxDynamicSharedMemorySize, MM_SMEM);
    cudaFuncSetAttribute(mm_tc<5,2,0>, cudaFuncAttributeMaxDynamicSharedMemorySize, MM_SMEM);

    // one fused weight-prep launch
    prep_w<<<13824, 256>>>(wbf, w_qconv, w_kvconv, saq_qkv, sakv_qkv, saq_proj, sakv_proj,
                           ca_q, ca_k, ca_v, ca_proj, leff_in, leff_out);

    dim3 gC(8, 2, NB), gQKV(8, 6, NB), gKV(8, 4, NB), gONE(8, 2, NB), gHID(8, 8, NB);
    dim3 gLN(32, NB), gATT(16, 4, NB), gDW(4, 32, NB);

    // ---- q branch ----
    mm_tc<3,1,0><<<gC, 256, MM_SMEM>>>(wbf+WC3, wbf+WC3+SP3, aop, nullptr, nullptr, 0,
        qbr, nullptr, nullptr, nullptr, nullptr, nullptr, 2304, 256, 256, 0, 0);
    ln_kernel<<<gLN, 256>>>(qbr, lnq1_w, lnq1_b, blnh, blnl);
    mm_tc<0,0,1><<<gQKV, 256, MM_SMEM>>>(wbf+WSAQ, wbf+WSAQ+SPQKV, nullptr, blnh, blnl, 256,
        nullptr, nullptr, bqk, bqk + 4194304, bvh, bvl, 256, 0, 512, 3, 4);
    attn_mma<<<gATT, 128, ATT_SMEM>>>(bqk, bqk + 4194304, 512,
        bqk + 256, bqk + 4194304 + 256, 512, bvh, bvl, batth, battl);
    mm_tc<0,0,1><<<gC, 256, MM_SMEM>>>(wbf+WSAQP, wbf+WSAQP+SPCC, nullptr, batth, battl, 256,
        qbr, qbr, nullptr, nullptr, nullptr, nullptr, 256, 0, 256, 0, 0);

    // ---- kv branch ----
    mm_tc<5,2,0><<<gC, 256, MM_SMEM>>>(wbf+WC5, wbf+WC5+SP5, dop, nullptr, nullptr, 0,
        kvbr, nullptr, nullptr, nullptr, nullptr, nullptr, 6400, 256, 256, 0, 0);
    ln_kernel<<<gLN, 256>>>(kvbr, lnkv1_w, lnkv1_b, blnh, blnl);
    mm_tc<0,0,1><<<gQKV, 256, MM_SMEM>>>(wbf+WSAKV, wbf+WSAKV+SPQKV, nullptr, blnh, blnl, 256,
        nullptr, nullptr, bqk, bqk + 4194304, bvh, bvl, 256, 0, 512, 3, 4);
    attn_mma<<<gATT, 128, ATT_SMEM>>>(bqk, bqk + 4194304, 512,
        bqk + 256, bqk + 4194304 + 256, 512, bvh, bvl, batth, battl);
    mm_tc<0,0,1><<<gC, 256, MM_SMEM>>>(wbf+WSAKVP, wbf+WSAKVP+SPCC, nullptr, batth, battl, 256,
        kvbr, kvbr, nullptr, nullptr, nullptr, nullptr, 256, 0, 256, 0, 0);

    // ---- cross attention ----
    ln_kernel<<<gLN, 256>>>(qbr, lnq2_w, lnq2_b, blnh, blnl);
    mm_tc<0,0,1><<<gONE, 256, MM_SMEM>>>(wbf+WCAQ, wbf+WCAQ+SPCC, nullptr, blnh, blnl, 256,
        nullptr, nullptr, bqk, bqk + 2097152, nullptr, nullptr, 256, 0, 256, 1, 0);
    ln_kernel<<<gLN, 256>>>(kvbr, lnkv2_w, lnkv2_b, blnh, blnl);
    mm_tc<0,0,1><<<gKV, 256, MM_SMEM>>>(wbf+WCAKV, wbf+WCAKV+SPKV, nullptr, blnh, blnl, 256,
        nullptr, nullptr, bqk + 4194304, bqk + 6291456, bvh, bvl, 256, 0, 256, 3, 2);
    attn_mma<<<gATT, 128, ATT_SMEM>>>(bqk, bqk + 2097152, 256,
        bqk + 4194304, bqk + 6291456, 256, bvh, bvl, batth, battl);
    mm_tc<0,0,1><<<gC, 256, MM_SMEM>>>(wbf+WCAP, wbf+WCAP+SPCC, nullptr, batth, battl, 256,
        out, qbr, nullptr, nullptr, nullptr, nullptr, 256, 0, 256, 0, 0);

    // ---- LeFF ----
    ln_kernel<<<gLN, 256>>>(out, lnffn_w, lnffn_b, blnh, blnl);
    mm_tc<0,0,1><<<gHID, 256, MM_SMEM>>>(wbf+WLIN, wbf+WLIN+SPLF, nullptr, blnh, blnl, 256,
        h1, nullptr, nullptr, nullptr, nullptr, nullptr, 256, 0, 1024, 0, 0);
    dwconv_gelu_tok<<<gDW, 256>>>(h1, leff_dw, dwh, dwl);
    mm_tc<0,0,1><<<gC, 256, MM_SMEM>>>(wbf+WLOUT, wbf+WLOUT+SPLF, nullptr, dwh, dwl, 1024,
        out, out, nullptr, nullptr, nullptr, nullptr, 1024, 0, 256, 0, 0);
}